// round 6
// baseline (speedup 1.0000x reference)
#include <cuda_runtime.h>
#include <math.h>

#define Bn 8
#define HW 4096
#define Mm 32768   // B*HW
#define HD 64

// Scratch (static device globals; no allocation allowed)
__device__ __align__(16) float g_qkv[9u * Mm * HD];   // [s*3+i][m][c]
__device__ __align__(16) float g_off[2][Mm * 18];     // offsets for dil 2,3
__device__ __align__(16) float g_defk[2][Mm * HD];    // deformed k
__device__ __align__(16) float g_defv[2][Mm * HD];    // deformed v
__device__ __align__(16) float g_attn[Mm * 192];      // attention outputs

// ---------------------------------------------------------------------------
// SGEMM: C[m,n] = sum_k A[m,k] * Bw[n,k]; 128x64 tile, 8x4 micro, k-chunk 16.
// mode 0: scatter into g_qkv[(n/64)][m][n%64]   (qkv projection, N=576)
// mode 1: Cout[m*192+n] = acc + bias[n], A taken from g_attn (final proj)
// ---------------------------------------------------------------------------
__global__ __launch_bounds__(256) void sgemm_kernel(
    const float* __restrict__ A, const float* __restrict__ Bw,
    const float* __restrict__ bias, float* __restrict__ Cout, int mode)
{
    __shared__ __align__(16) float As[16][132];
    __shared__ __align__(16) float Bs[16][68];
    int tid = threadIdx.x;
    int tx = tid & 15, ty = tid >> 4;    // tx: 4 n's, ty: 8 m's
    int m0 = blockIdx.x * 128, n0 = blockIdx.y * 64;
    const float* Ap = (mode == 0) ? A : g_attn;
    float acc[8][4] = {};

    for (int k0 = 0; k0 < 192; k0 += 16) {
        #pragma unroll
        for (int s = 0; s < 2; s++) {
            int u = tid + s * 256;
            int mm = u >> 2, kq = u & 3;
            float4 av = *(const float4*)&Ap[(size_t)(m0 + mm) * 192 + k0 + kq * 4];
            As[kq * 4 + 0][mm] = av.x;
            As[kq * 4 + 1][mm] = av.y;
            As[kq * 4 + 2][mm] = av.z;
            As[kq * 4 + 3][mm] = av.w;
        }
        {
            int nn = tid >> 2, kq = tid & 3;
            float4 bv = *(const float4*)&Bw[(size_t)(n0 + nn) * 192 + k0 + kq * 4];
            Bs[kq * 4 + 0][nn] = bv.x;
            Bs[kq * 4 + 1][nn] = bv.y;
            Bs[kq * 4 + 2][nn] = bv.z;
            Bs[kq * 4 + 3][nn] = bv.w;
        }
        __syncthreads();
        #pragma unroll
        for (int kk = 0; kk < 16; kk++) {
            float4 a0 = *(const float4*)&As[kk][ty * 8];
            float4 a1 = *(const float4*)&As[kk][ty * 8 + 4];
            float4 b  = *(const float4*)&Bs[kk][tx * 4];
            float a[8] = {a0.x, a0.y, a0.z, a0.w, a1.x, a1.y, a1.z, a1.w};
            float bb[4] = {b.x, b.y, b.z, b.w};
            #pragma unroll
            for (int i = 0; i < 8; i++)
                #pragma unroll
                for (int j = 0; j < 4; j++)
                    acc[i][j] += a[i] * bb[j];
        }
        __syncthreads();
    }

    if (mode == 0) {
        size_t bufbase = (size_t)blockIdx.y * Mm * 64;
        #pragma unroll
        for (int i = 0; i < 8; i++) {
            int m = m0 + ty * 8 + i;
            float4 v = {acc[i][0], acc[i][1], acc[i][2], acc[i][3]};
            *(float4*)&g_qkv[bufbase + (size_t)m * 64 + tx * 4] = v;
        }
    } else {
        float4 b4 = *(const float4*)&bias[n0 + tx * 4];
        #pragma unroll
        for (int i = 0; i < 8; i++) {
            int m = m0 + ty * 8 + i;
            float4 v = {acc[i][0] + b4.x, acc[i][1] + b4.y,
                        acc[i][2] + b4.z, acc[i][3] + b4.w};
            *(float4*)&Cout[(size_t)m * 192 + n0 + tx * 4] = v;
        }
    }
}

// ---------------------------------------------------------------------------
// Offset conv: dilated 3x3 conv on k branch, 64 -> 18 ch, zero pad = dil.
// blockIdx.y selects dil (2 or 3). Block: 32 px (8 warps x 4 px),
// lanes = (px_sub 4) x (channel-octet 8). Weights transposed in smem.
// ---------------------------------------------------------------------------
__global__ __launch_bounds__(256) void offconv_kernel(
    const float* __restrict__ ow2, const float* __restrict__ ob2,
    const float* __restrict__ ow3, const float* __restrict__ ob3)
{
    __shared__ __align__(16) float ws[18 * 612];
    int dil_idx = blockIdx.y;
    int dil = dil_idx + 2;
    const float* ow = dil_idx ? ow3 : ow2;
    const float* ob = dil_idx ? ob3 : ob2;
    const float* kin = &g_qkv[(size_t)(4 + dil_idx) * Mm * HD];
    float* offout = g_off[dil_idx];
    int tid = threadIdx.x;

    for (int i = tid; i < 18 * 576; i += 256) {
        int oc = i / 576, r = i % 576, c = r / 9, kk = r % 9;
        ws[oc * 612 + kk * 68 + c] = ow[i];
    }
    __syncthreads();

    int wr = tid >> 5, lane = tid & 31;
    int pxs = lane >> 3, cq = lane & 7;
    int m = blockIdx.x * 32 + wr * 4 + pxs;
    int b = m >> 12, hw = m & 4095, h = hw >> 6, w = hw & 63;

    float acc[18];
    #pragma unroll
    for (int oc = 0; oc < 18; oc++) acc[oc] = 0.f;

    for (int kk = 0; kk < 9; kk++) {
        int y = h + (kk / 3 - 1) * dil;
        int x = w + (kk % 3 - 1) * dil;
        float4 k0 = {0.f, 0.f, 0.f, 0.f}, k1 = {0.f, 0.f, 0.f, 0.f};
        if ((unsigned)y < 64u && (unsigned)x < 64u) {
            const float* kp = kin + (size_t)((b << 12) + (y << 6) + x) * 64 + cq * 8;
            k0 = *(const float4*)kp;
            k1 = *(const float4*)(kp + 4);
        }
        const float* wsk = ws + kk * 68 + cq * 8;
        #pragma unroll
        for (int oc = 0; oc < 18; oc++) {
            float4 w0 = *(const float4*)(wsk + oc * 612);
            float4 w1 = *(const float4*)(wsk + oc * 612 + 4);
            acc[oc] += k0.x * w0.x + k0.y * w0.y + k0.z * w0.z + k0.w * w0.w
                     + k1.x * w1.x + k1.y * w1.y + k1.z * w1.z + k1.w * w1.w;
        }
    }
    #pragma unroll
    for (int oc = 0; oc < 18; oc++) {
        float a = acc[oc];
        a += __shfl_xor_sync(0xffffffffu, a, 1);
        a += __shfl_xor_sync(0xffffffffu, a, 2);
        a += __shfl_xor_sync(0xffffffffu, a, 4);
        acc[oc] = a;
    }
    if (cq == 0) {
        #pragma unroll
        for (int oc = 0; oc < 18; oc++)
            offout[(size_t)m * 18 + oc] = acc[oc] + ob[oc];
    }
}

// ---------------------------------------------------------------------------
// Deformable conv for k AND v. blockIdx.y selects dil. Block: 32 px x 64 out.
// Sampling: task = (tensor, px, tap, ch-quad): 4 predicated LDG.128 corner
// reads + register bilinear blend + 4 scalar STS. NO shuffles.
// GEMM: thread = (tx: 4 px) x (ty: 2 out) x 2 tensors = 16 acc, K = 8 x 72.
// ---------------------------------------------------------------------------
__global__ __launch_bounds__(256) void deform_kernel(
    const float* __restrict__ dw2, const float* __restrict__ db2,
    const float* __restrict__ dw3, const float* __restrict__ db3)
{
    __shared__ __align__(16) float s_k[72][36];
    __shared__ __align__(16) float s_v[72][36];
    __shared__ float w_s[64 * 73];
    __shared__ __align__(16) int4   s_base4[32 * 9];
    __shared__ __align__(16) float4 s_wgt4[32 * 9];

    int dil_idx = blockIdx.y;
    int dil = dil_idx + 2;
    const float* dw = dil_idx ? dw3 : dw2;
    const float* db = dil_idx ? db3 : db2;
    const float* kin = &g_qkv[(size_t)(4 + dil_idx) * Mm * HD];
    const float* vin = &g_qkv[(size_t)(7 + dil_idx) * Mm * HD];
    const float* off = g_off[dil_idx];
    float* kout = g_defk[dil_idx];
    float* vout = g_defv[dil_idx];

    int tid = threadIdx.x;
    int m0 = blockIdx.x * 32;
    int bpix = m0 & ~4095;   // batch base (block within one batch)

    // precompute bilinear corners for 32 px x 9 taps
    for (int i = tid; i < 32 * 9; i += 256) {
        int px = i / 9, kk = i % 9;
        int m = m0 + px;
        int hw = m & 4095;
        int h = hw >> 6, w = hw & 63;
        float oy = off[(size_t)m * 18 + kk * 2 + 0];
        float ox = off[(size_t)m * 18 + kk * 2 + 1];
        float py  = (float)(h + (kk / 3 - 1) * dil) + oy;
        float pxf = (float)(w + (kk % 3 - 1) * dil) + ox;
        float y0f = floorf(py), x0f = floorf(pxf);
        float wy = py - y0f, wx = pxf - x0f;
        int y0 = (int)y0f, x0 = (int)x0f;
        int yv0 = ((unsigned)y0 < 64u), yv1 = ((unsigned)(y0 + 1) < 64u);
        int xv0 = ((unsigned)x0 < 64u), xv1 = ((unsigned)(x0 + 1) < 64u);
        int4 bs;
        bs.x = (yv0 && xv0) ? ((y0 << 6) + x0)           : -1;
        bs.y = (yv0 && xv1) ? ((y0 << 6) + x0 + 1)       : -1;
        bs.z = (yv1 && xv0) ? (((y0 + 1) << 6) + x0)     : -1;
        bs.w = (yv1 && xv1) ? (((y0 + 1) << 6) + x0 + 1) : -1;
        float4 wt;
        wt.x = (1.f - wy) * (1.f - wx);
        wt.y = (1.f - wy) * wx;
        wt.z = wy * (1.f - wx);
        wt.w = wy * wx;
        s_base4[i] = bs;
        s_wgt4[i]  = wt;
    }
    __syncthreads();

    int tx = tid & 7, ty = tid >> 3;       // tx: px-quad, ty: out-pair

    float b0 = db[ty * 2], b1 = db[ty * 2 + 1];
    float ak0[4], ak1[4], av0[4], av1[4];
    #pragma unroll
    for (int j = 0; j < 4; j++) { ak0[j] = b0; ak1[j] = b1; av0[j] = b0; av1[j] = b1; }

    for (int ch = 0; ch < 8; ch++) {
        // stage weight chunk: w_s[o][di], di = lc*9+kk (dw is [o][c][kk])
        for (int i = tid; i < 64 * 72; i += 256) {
            int o = i / 72, di = i % 72;
            w_s[o * 73 + di] = dw[o * 576 + ch * 72 + di];
        }
        // sampling: 1152 tasks = (tensor 2) x (px*9 = 288) x (quad 2)
        for (int t = tid; t < 1152; t += 256) {
            int quad = t & 1;
            int pk = t >> 1;                 // 0..575
            int tsel = pk >= 288;
            int p = tsel ? pk - 288 : pk;    // = px*9 + kk
            int px = p / 9, kk = p - px * 9;
            const float* src = tsel ? vin : kin;
            float* dst = tsel ? &s_v[0][0] : &s_k[0][0];
            int4 bs = s_base4[p];
            float4 wt = s_wgt4[p];
            int c0 = ch * 8 + quad * 4;
            float ax = 0.f, ay = 0.f, az = 0.f, aw = 0.f;
            if (bs.x >= 0) {
                float4 cv = *(const float4*)&src[(size_t)(bpix + bs.x) * 64 + c0];
                ax += wt.x * cv.x; ay += wt.x * cv.y; az += wt.x * cv.z; aw += wt.x * cv.w;
            }
            if (bs.y >= 0) {
                float4 cv = *(const float4*)&src[(size_t)(bpix + bs.y) * 64 + c0];
                ax += wt.y * cv.x; ay += wt.y * cv.y; az += wt.y * cv.z; aw += wt.y * cv.w;
            }
            if (bs.z >= 0) {
                float4 cv = *(const float4*)&src[(size_t)(bpix + bs.z) * 64 + c0];
                ax += wt.z * cv.x; ay += wt.z * cv.y; az += wt.z * cv.z; aw += wt.z * cv.w;
            }
            if (bs.w >= 0) {
                float4 cv = *(const float4*)&src[(size_t)(bpix + bs.w) * 64 + c0];
                ax += wt.w * cv.x; ay += wt.w * cv.y; az += wt.w * cv.z; aw += wt.w * cv.w;
            }
            // di = (quad*4 + j)*9 + kk, row stride 36
            int base = (quad * 36 + kk) * 36 + px;
            dst[base]            = ax;
            dst[base + 9  * 36]  = ay;
            dst[base + 18 * 36]  = az;
            dst[base + 27 * 36]  = aw;
        }
        __syncthreads();
        #pragma unroll 4
        for (int di = 0; di < 72; di++) {
            float4 k4 = *(const float4*)&s_k[di][tx * 4];
            float4 v4 = *(const float4*)&s_v[di][tx * 4];
            float w0 = w_s[(ty * 2) * 73 + di];
            float w1 = w_s[(ty * 2 + 1) * 73 + di];
            ak0[0] += k4.x * w0; ak1[0] += k4.x * w1;
            ak0[1] += k4.y * w0; ak1[1] += k4.y * w1;
            ak0[2] += k4.z * w0; ak1[2] += k4.z * w1;
            ak0[3] += k4.w * w0; ak1[3] += k4.w * w1;
            av0[0] += v4.x * w0; av1[0] += v4.x * w1;
            av0[1] += v4.y * w0; av1[1] += v4.y * w1;
            av0[2] += v4.z * w0; av1[2] += v4.z * w1;
            av0[3] += v4.w * w0; av1[3] += v4.w * w1;
        }
        __syncthreads();
    }
    #pragma unroll
    for (int j = 0; j < 4; j++) {
        int m = m0 + tx * 4 + j;
        float2 kv = {ak0[j], ak1[j]};
        float2 vv = {av0[j], av1[j]};
        *(float2*)&kout[(size_t)m * 64 + ty * 2] = kv;
        *(float2*)&vout[(size_t)m * 64 + ty * 2] = vv;
    }
}

// ---------------------------------------------------------------------------
// Attention: warp per pixel, grid (4096, 3 dilations). 9-tap softmax.
// float2-vectorized channel loads (lane covers ch 2*lane, 2*lane+1).
// OOB taps contribute logit EXACTLY 0 (zero-padded unfold) and v = 0.
// ---------------------------------------------------------------------------
__global__ __launch_bounds__(256) void attn_kernel()
{
    int dil_idx = blockIdx.y;
    int dil = dil_idx + 1;
    int warp = threadIdx.x >> 5, lane = threadIdx.x & 31;
    int m = blockIdx.x * 8 + warp;
    int b = m >> 12, hw = m & 4095, h = hw >> 6, w = hw & 63;
    const float* q = &g_qkv[(size_t)dil_idx * Mm * HD];
    const float *kb, *vb;
    if (dil_idx == 0) {
        kb = &g_qkv[(size_t)3 * Mm * HD];
        vb = &g_qkv[(size_t)6 * Mm * HD];
    } else {
        kb = g_defk[dil_idx - 1];
        vb = g_defv[dil_idx - 1];
    }
    float2 q01 = *(const float2*)&q[(size_t)m * 64 + lane * 2];
    float eg[9];
    int nb[9];
    float mx = -1e30f;
    #pragma unroll
    for (int j = 0; j < 9; j++) {
        int y = h + (j / 3 - 1) * dil;
        int x = w + (j % 3 - 1) * dil;
        bool valid = ((unsigned)y < 64u) && ((unsigned)x < 64u);
        float p = 0.f;
        int base = -1;
        if (valid) {
            base = (b << 12) + (y << 6) + x;
            float2 k2 = *(const float2*)&kb[(size_t)base * 64 + lane * 2];
            p = q01.x * k2.x + q01.y * k2.y;
        }
        nb[j] = base;
        #pragma unroll
        for (int s = 16; s; s >>= 1) p += __shfl_xor_sync(0xffffffffu, p, s);
        eg[j] = p * 0.125f;
        mx = fmaxf(mx, eg[j]);
    }
    float sum = 0.f;
    #pragma unroll
    for (int j = 0; j < 9; j++) { eg[j] = expf(eg[j] - mx); sum += eg[j]; }
    float inv = 1.f / sum;
    float o0 = 0.f, o1 = 0.f;
    #pragma unroll
    for (int j = 0; j < 9; j++) {
        if (nb[j] >= 0) {
            float a = eg[j] * inv;
            float2 v2 = *(const float2*)&vb[(size_t)nb[j] * 64 + lane * 2];
            o0 += a * v2.x;
            o1 += a * v2.y;
        }
    }
    float2 o = {o0, o1};
    *(float2*)&g_attn[(size_t)m * 192 + dil_idx * 64 + lane * 2] = o;
}

// ---------------------------------------------------------------------------
extern "C" void kernel_launch(void* const* d_in, const int* in_sizes, int n_in,
                              void* d_out, int out_size)
{
    const float* x      = (const float*)d_in[0];
    const float* qkv_w  = (const float*)d_in[1];
    const float* proj_w = (const float*)d_in[2];
    const float* proj_b = (const float*)d_in[3];
    const float* off_w2 = (const float*)d_in[4];
    const float* off_b2 = (const float*)d_in[5];
    const float* def_w2 = (const float*)d_in[6];
    const float* def_b2 = (const float*)d_in[7];
    const float* off_w3 = (const float*)d_in[8];
    const float* off_b3 = (const float*)d_in[9];
    const float* def_w3 = (const float*)d_in[10];
    const float* def_b3 = (const float*)d_in[11];
    float* out = (float*)d_out;

    // 1) qkv projection: (32768 x 192) @ (192 x 576) -> per-branch buffers
    sgemm_kernel<<<dim3(256, 9), 256>>>(x, qkv_w, nullptr, nullptr, 0);

    // 2) offset convs (dil 2, 3 merged)
    offconv_kernel<<<dim3(1024, 2), 256>>>(off_w2, off_b2, off_w3, off_b3);

    // 3) deformable conv on k and v (dil 2, 3 merged)
    deform_kernel<<<dim3(1024, 2), 256>>>(def_w2, def_b2, def_w3, def_b3);

    // 4) local attention, all 3 dilations
    attn_kernel<<<dim3(4096, 3), 256>>>();

    // 5) output projection + bias -> d_out
    sgemm_kernel<<<dim3(256, 3), 256>>>(nullptr, proj_w, proj_b, out, 1);
}

// round 7
// speedup vs baseline: 1.4845x; 1.4845x over previous
#include <cuda_runtime.h>
#include <math.h>

#define Bn 8
#define HW 4096
#define Mm 32768   // B*HW
#define HD 64

// Scratch (static device globals; no allocation allowed)
__device__ __align__(16) float g_qkv[9u * Mm * HD];   // [s*3+i][m][c]
__device__ __align__(16) float g_off[2][Mm * 18];     // offsets for dil 2,3
__device__ __align__(16) float g_defk[2][Mm * HD];    // deformed k
__device__ __align__(16) float g_defv[2][Mm * HD];    // deformed v
__device__ __align__(16) float g_attn[Mm * 192];      // attention outputs

// ---------------------------------------------------------------------------
// SGEMM: C[m,n] = sum_k A[m,k] * Bw[n,k]; 128x64 tile, 8x4 micro, k-chunk 16.
// mode 0: scatter into g_qkv[(n/64)][m][n%64]   (qkv projection, N=576)
// mode 1: Cout[m*192+n] = acc + bias[n], A taken from g_attn (final proj)
// ---------------------------------------------------------------------------
__global__ __launch_bounds__(256) void sgemm_kernel(
    const float* __restrict__ A, const float* __restrict__ Bw,
    const float* __restrict__ bias, float* __restrict__ Cout, int mode)
{
    __shared__ __align__(16) float As[16][132];
    __shared__ __align__(16) float Bs[16][68];
    int tid = threadIdx.x;
    int tx = tid & 15, ty = tid >> 4;    // tx: 4 n's, ty: 8 m's
    int m0 = blockIdx.x * 128, n0 = blockIdx.y * 64;
    const float* Ap = (mode == 0) ? A : g_attn;
    float acc[8][4] = {};

    for (int k0 = 0; k0 < 192; k0 += 16) {
        #pragma unroll
        for (int s = 0; s < 2; s++) {
            int u = tid + s * 256;
            int mm = u >> 2, kq = u & 3;
            float4 av = *(const float4*)&Ap[(size_t)(m0 + mm) * 192 + k0 + kq * 4];
            As[kq * 4 + 0][mm] = av.x;
            As[kq * 4 + 1][mm] = av.y;
            As[kq * 4 + 2][mm] = av.z;
            As[kq * 4 + 3][mm] = av.w;
        }
        {
            int nn = tid >> 2, kq = tid & 3;
            float4 bv = *(const float4*)&Bw[(size_t)(n0 + nn) * 192 + k0 + kq * 4];
            Bs[kq * 4 + 0][nn] = bv.x;
            Bs[kq * 4 + 1][nn] = bv.y;
            Bs[kq * 4 + 2][nn] = bv.z;
            Bs[kq * 4 + 3][nn] = bv.w;
        }
        __syncthreads();
        #pragma unroll
        for (int kk = 0; kk < 16; kk++) {
            float4 a0 = *(const float4*)&As[kk][ty * 8];
            float4 a1 = *(const float4*)&As[kk][ty * 8 + 4];
            float4 b  = *(const float4*)&Bs[kk][tx * 4];
            float a[8] = {a0.x, a0.y, a0.z, a0.w, a1.x, a1.y, a1.z, a1.w};
            float bb[4] = {b.x, b.y, b.z, b.w};
            #pragma unroll
            for (int i = 0; i < 8; i++)
                #pragma unroll
                for (int j = 0; j < 4; j++)
                    acc[i][j] += a[i] * bb[j];
        }
        __syncthreads();
    }

    if (mode == 0) {
        size_t bufbase = (size_t)blockIdx.y * Mm * 64;
        #pragma unroll
        for (int i = 0; i < 8; i++) {
            int m = m0 + ty * 8 + i;
            float4 v = {acc[i][0], acc[i][1], acc[i][2], acc[i][3]};
            *(float4*)&g_qkv[bufbase + (size_t)m * 64 + tx * 4] = v;
        }
    } else {
        float4 b4 = *(const float4*)&bias[n0 + tx * 4];
        #pragma unroll
        for (int i = 0; i < 8; i++) {
            int m = m0 + ty * 8 + i;
            float4 v = {acc[i][0] + b4.x, acc[i][1] + b4.y,
                        acc[i][2] + b4.z, acc[i][3] + b4.w};
            *(float4*)&Cout[(size_t)m * 192 + n0 + tx * 4] = v;
        }
    }
}

// ---------------------------------------------------------------------------
// Offset conv: dilated 3x3 conv on k branch, 64 -> 18 ch, zero pad = dil.
// blockIdx.y selects dil (2 or 3). Block: 32 px (8 warps x 4 px),
// lanes = (px_sub 4) x (channel-octet 8). Weights transposed in smem.
// ---------------------------------------------------------------------------
__global__ __launch_bounds__(256) void offconv_kernel(
    const float* __restrict__ ow2, const float* __restrict__ ob2,
    const float* __restrict__ ow3, const float* __restrict__ ob3)
{
    __shared__ __align__(16) float ws[18 * 612];
    int dil_idx = blockIdx.y;
    int dil = dil_idx + 2;
    const float* ow = dil_idx ? ow3 : ow2;
    const float* ob = dil_idx ? ob3 : ob2;
    const float* kin = &g_qkv[(size_t)(4 + dil_idx) * Mm * HD];
    float* offout = g_off[dil_idx];
    int tid = threadIdx.x;

    for (int i = tid; i < 18 * 576; i += 256) {
        int oc = i / 576, r = i % 576, c = r / 9, kk = r % 9;
        ws[oc * 612 + kk * 68 + c] = ow[i];
    }
    __syncthreads();

    int wr = tid >> 5, lane = tid & 31;
    int pxs = lane >> 3, cq = lane & 7;
    int m = blockIdx.x * 32 + wr * 4 + pxs;
    int b = m >> 12, hw = m & 4095, h = hw >> 6, w = hw & 63;

    float acc[18];
    #pragma unroll
    for (int oc = 0; oc < 18; oc++) acc[oc] = 0.f;

    for (int kk = 0; kk < 9; kk++) {
        int y = h + (kk / 3 - 1) * dil;
        int x = w + (kk % 3 - 1) * dil;
        float4 k0 = {0.f, 0.f, 0.f, 0.f}, k1 = {0.f, 0.f, 0.f, 0.f};
        if ((unsigned)y < 64u && (unsigned)x < 64u) {
            const float* kp = kin + (size_t)((b << 12) + (y << 6) + x) * 64 + cq * 8;
            k0 = *(const float4*)kp;
            k1 = *(const float4*)(kp + 4);
        }
        const float* wsk = ws + kk * 68 + cq * 8;
        #pragma unroll
        for (int oc = 0; oc < 18; oc++) {
            float4 w0 = *(const float4*)(wsk + oc * 612);
            float4 w1 = *(const float4*)(wsk + oc * 612 + 4);
            acc[oc] += k0.x * w0.x + k0.y * w0.y + k0.z * w0.z + k0.w * w0.w
                     + k1.x * w1.x + k1.y * w1.y + k1.z * w1.z + k1.w * w1.w;
        }
    }
    #pragma unroll
    for (int oc = 0; oc < 18; oc++) {
        float a = acc[oc];
        a += __shfl_xor_sync(0xffffffffu, a, 1);
        a += __shfl_xor_sync(0xffffffffu, a, 2);
        a += __shfl_xor_sync(0xffffffffu, a, 4);
        acc[oc] = a;
    }
    if (cq == 0) {
        #pragma unroll
        for (int oc = 0; oc < 18; oc++)
            offout[(size_t)m * 18 + oc] = acc[oc] + ob[oc];
    }
}

// ---------------------------------------------------------------------------
// Deformable conv for k AND v. blockIdx.y selects dil. Block: 32 px x 64 out.
// Full sampled tile (2 x 32px x 576) lives in dynamic smem; sampled ONCE with
// 100%-efficient LDG.128 (lanes span two full 256B pixel rows per corner) and
// contiguous STS.128. GEMM: di = kk*64+c, thread = 2px x 4out x 2tensors,
// float4 K-vectorized -> FFMA-bound. Output staged via smem, STG.128.
// ---------------------------------------------------------------------------
#define S_ROW 588                 // 576 + 12 pad (16B aligned, bank-skewed)
#define DEF_SMEM (2 * 32 * S_ROW * 4 + 64 * 76 * 4 + 288 * 32)

__global__ __launch_bounds__(256) void deform_kernel(
    const float* __restrict__ dw2, const float* __restrict__ db2,
    const float* __restrict__ dw3, const float* __restrict__ db3)
{
    extern __shared__ __align__(16) float smem[];
    float*  s_k  = smem;                       // [32][S_ROW]
    float*  s_v  = smem + 32 * S_ROW;          // [32][S_ROW]
    float*  w_s  = smem + 64 * S_ROW;          // [64][76]
    int4*   s_b4 = (int4*)(w_s + 64 * 76);     // [288]
    float4* s_w4 = (float4*)(s_b4 + 288);      // [288]

    int dil_idx = blockIdx.y;
    int dil = dil_idx + 2;
    const float* dw = dil_idx ? dw3 : dw2;
    const float* db = dil_idx ? db3 : db2;
    const float* kin = &g_qkv[(size_t)(4 + dil_idx) * Mm * HD];
    const float* vin = &g_qkv[(size_t)(7 + dil_idx) * Mm * HD];
    const float* off = g_off[dil_idx];
    float* kout = g_defk[dil_idx];
    float* vout = g_defv[dil_idx];

    int tid = threadIdx.x;
    int m0 = blockIdx.x * 32;
    int bpix = m0 & ~4095;      // batch base (block within one batch)

    // ---- corner precompute: 32 px x 9 taps ----
    for (int i = tid; i < 288; i += 256) {
        int px = i / 9, kk = i % 9;
        int m = m0 + px;
        int hw = m & 4095;
        int h = hw >> 6, w = hw & 63;
        float oy = off[(size_t)m * 18 + kk * 2 + 0];
        float ox = off[(size_t)m * 18 + kk * 2 + 1];
        float py  = (float)(h + (kk / 3 - 1) * dil) + oy;
        float pxf = (float)(w + (kk % 3 - 1) * dil) + ox;
        float y0f = floorf(py), x0f = floorf(pxf);
        float wy = py - y0f, wx = pxf - x0f;
        int y0 = (int)y0f, x0 = (int)x0f;
        int yv0 = ((unsigned)y0 < 64u), yv1 = ((unsigned)(y0 + 1) < 64u);
        int xv0 = ((unsigned)x0 < 64u), xv1 = ((unsigned)(x0 + 1) < 64u);
        int4 bs;
        bs.x = (yv0 && xv0) ? ((y0 << 6) + x0)           : -1;
        bs.y = (yv0 && xv1) ? ((y0 << 6) + x0 + 1)       : -1;
        bs.z = (yv1 && xv0) ? (((y0 + 1) << 6) + x0)     : -1;
        bs.w = (yv1 && xv1) ? (((y0 + 1) << 6) + x0 + 1) : -1;
        float4 wt;
        wt.x = (1.f - wy) * (1.f - wx);
        wt.y = (1.f - wy) * wx;
        wt.z = wy * (1.f - wx);
        wt.w = wy * wx;
        s_b4[i] = bs;
        s_w4[i] = wt;
    }
    __syncthreads();

    // ---- sampling (once): warps 0-3 -> k, 4-7 -> v; 72 (px,tap) per warp ----
    {
        int warp = tid >> 5, lane = tid & 31;
        int slot = lane >> 4;             // which of 2 (px,tap) per iter
        int cq   = lane & 15;             // channel quad
        const float* src = (warp >= 4) ? vin : kin;
        float* dst = (warp >= 4) ? s_v : s_k;
        int pbase = (warp & 3) * 72;
        const float* rowbase = src + (size_t)bpix * 64 + cq * 4;
        #pragma unroll 3
        for (int s = 0; s < 36; s++) {
            int p = pbase + 2 * s + slot;
            int4 bs = s_b4[p];
            float4 wt = s_w4[p];
            int px = p / 9, kk = p - px * 9;
            float4 a = {0.f, 0.f, 0.f, 0.f};
            if (bs.x >= 0) {
                float4 v = *(const float4*)(rowbase + (size_t)bs.x * 64);
                a.x += wt.x * v.x; a.y += wt.x * v.y; a.z += wt.x * v.z; a.w += wt.x * v.w;
            }
            if (bs.y >= 0) {
                float4 v = *(const float4*)(rowbase + (size_t)bs.y * 64);
                a.x += wt.y * v.x; a.y += wt.y * v.y; a.z += wt.y * v.z; a.w += wt.y * v.w;
            }
            if (bs.z >= 0) {
                float4 v = *(const float4*)(rowbase + (size_t)bs.z * 64);
                a.x += wt.z * v.x; a.y += wt.z * v.y; a.z += wt.z * v.z; a.w += wt.z * v.w;
            }
            if (bs.w >= 0) {
                float4 v = *(const float4*)(rowbase + (size_t)bs.w * 64);
                a.x += wt.w * v.x; a.y += wt.w * v.y; a.z += wt.w * v.z; a.w += wt.w * v.w;
            }
            *(float4*)&dst[px * S_ROW + kk * 64 + cq * 4] = a;
        }
    }
    __syncthreads();

    // ---- GEMM: di = kk*64+c; thread = 2 px x 4 out x 2 tensors ----
    int tx = tid & 15;          // px pair {tx, tx+16}
    int ty = tid >> 4;          // out set {ty, ty+16, ty+32, ty+48}
    float accK[2][4], accV[2][4];
    #pragma unroll
    for (int j = 0; j < 4; j++) {
        float bv = db[ty + j * 16];
        accK[0][j] = bv; accK[1][j] = bv;
        accV[0][j] = bv; accV[1][j] = bv;
    }

    for (int ch = 0; ch < 8; ch++) {
        // stage weight chunk: w_s[o][i], di = ch*72+i, dw layout [o][c][kk]
        for (int idx = tid; idx < 64 * 72; idx += 256) {
            int o = idx / 72, i = idx - o * 72;
            int di = ch * 72 + i;
            int kk = di >> 6, c = di & 63;
            w_s[o * 76 + i] = dw[o * 576 + c * 9 + kk];
        }
        __syncthreads();
        #pragma unroll 3
        for (int i = 0; i < 72; i += 4) {
            int di = ch * 72 + i;
            float4 k0 = *(const float4*)&s_k[tx * S_ROW + di];
            float4 k1 = *(const float4*)&s_k[(tx + 16) * S_ROW + di];
            float4 v0 = *(const float4*)&s_v[tx * S_ROW + di];
            float4 v1 = *(const float4*)&s_v[(tx + 16) * S_ROW + di];
            #pragma unroll
            for (int j = 0; j < 4; j++) {
                float4 wv = *(const float4*)&w_s[(ty + j * 16) * 76 + i];
                accK[0][j] += k0.x * wv.x + k0.y * wv.y + k0.z * wv.z + k0.w * wv.w;
                accK[1][j] += k1.x * wv.x + k1.y * wv.y + k1.z * wv.z + k1.w * wv.w;
                accV[0][j] += v0.x * wv.x + v0.y * wv.y + v0.z * wv.z + v0.w * wv.w;
                accV[1][j] += v1.x * wv.x + v1.y * wv.y + v1.z * wv.z + v1.w * wv.w;
            }
        }
        __syncthreads();
    }

    // ---- output: stage via smem (reuse s_k), coalesced STG.128 ----
    float* so = s_k;    // [32][68]
    #pragma unroll
    for (int i = 0; i < 2; i++)
        #pragma unroll
        for (int j = 0; j < 4; j++)
            so[(tx + 16 * i) * 68 + ty + 16 * j] = accK[i][j];
    __syncthreads();
    for (int idx = tid; idx < 512; idx += 256) {
        int px = idx >> 4, q = idx & 15;
        float4 val = *(const float4*)&so[px * 68 + q * 4];
        *(float4*)&kout[(size_t)(m0 + px) * 64 + q * 4] = val;
    }
    __syncthreads();
    #pragma unroll
    for (int i = 0; i < 2; i++)
        #pragma unroll
        for (int j = 0; j < 4; j++)
            so[(tx + 16 * i) * 68 + ty + 16 * j] = accV[i][j];
    __syncthreads();
    for (int idx = tid; idx < 512; idx += 256) {
        int px = idx >> 4, q = idx & 15;
        float4 val = *(const float4*)&so[px * 68 + q * 4];
        *(float4*)&vout[(size_t)(m0 + px) * 64 + q * 4] = val;
    }
}

// ---------------------------------------------------------------------------
// Attention: warp per pixel, grid (4096, 3 dilations). 9-tap softmax.
// float2-vectorized channel loads. OOB taps contribute logit EXACTLY 0.
// ---------------------------------------------------------------------------
__global__ __launch_bounds__(256) void attn_kernel()
{
    int dil_idx = blockIdx.y;
    int dil = dil_idx + 1;
    int warp = threadIdx.x >> 5, lane = threadIdx.x & 31;
    int m = blockIdx.x * 8 + warp;
    int b = m >> 12, hw = m & 4095, h = hw >> 6, w = hw & 63;
    const float* q = &g_qkv[(size_t)dil_idx * Mm * HD];
    const float *kb, *vb;
    if (dil_idx == 0) {
        kb = &g_qkv[(size_t)3 * Mm * HD];
        vb = &g_qkv[(size_t)6 * Mm * HD];
    } else {
        kb = g_defk[dil_idx - 1];
        vb = g_defv[dil_idx - 1];
    }
    float2 q01 = *(const float2*)&q[(size_t)m * 64 + lane * 2];
    float eg[9];
    int nb[9];
    float mx = -1e30f;
    #pragma unroll
    for (int j = 0; j < 9; j++) {
        int y = h + (j / 3 - 1) * dil;
        int x = w + (j % 3 - 1) * dil;
        bool valid = ((unsigned)y < 64u) && ((unsigned)x < 64u);
        float p = 0.f;
        int base = -1;
        if (valid) {
            base = (b << 12) + (y << 6) + x;
            float2 k2 = *(const float2*)&kb[(size_t)base * 64 + lane * 2];
            p = q01.x * k2.x + q01.y * k2.y;
        }
        nb[j] = base;
        #pragma unroll
        for (int s = 16; s; s >>= 1) p += __shfl_xor_sync(0xffffffffu, p, s);
        eg[j] = p * 0.125f;
        mx = fmaxf(mx, eg[j]);
    }
    float sum = 0.f;
    #pragma unroll
    for (int j = 0; j < 9; j++) { eg[j] = expf(eg[j] - mx); sum += eg[j]; }
    float inv = 1.f / sum;
    float o0 = 0.f, o1 = 0.f;
    #pragma unroll
    for (int j = 0; j < 9; j++) {
        if (nb[j] >= 0) {
            float a = eg[j] * inv;
            float2 v2 = *(const float2*)&vb[(size_t)nb[j] * 64 + lane * 2];
            o0 += a * v2.x;
            o1 += a * v2.y;
        }
    }
    float2 o = {o0, o1};
    *(float2*)&g_attn[(size_t)m * 192 + dil_idx * 64 + lane * 2] = o;
}

// ---------------------------------------------------------------------------
extern "C" void kernel_launch(void* const* d_in, const int* in_sizes, int n_in,
                              void* d_out, int out_size)
{
    const float* x      = (const float*)d_in[0];
    const float* qkv_w  = (const float*)d_in[1];
    const float* proj_w = (const float*)d_in[2];
    const float* proj_b = (const float*)d_in[3];
    const float* off_w2 = (const float*)d_in[4];
    const float* off_b2 = (const float*)d_in[5];
    const float* def_w2 = (const float*)d_in[6];
    const float* def_b2 = (const float*)d_in[7];
    const float* off_w3 = (const float*)d_in[8];
    const float* off_b3 = (const float*)d_in[9];
    const float* def_w3 = (const float*)d_in[10];
    const float* def_b3 = (const float*)d_in[11];
    float* out = (float*)d_out;

    cudaFuncSetAttribute(deform_kernel,
                         cudaFuncAttributeMaxDynamicSharedMemorySize, DEF_SMEM);

    // 1) qkv projection: (32768 x 192) @ (192 x 576) -> per-branch buffers
    sgemm_kernel<<<dim3(256, 9), 256>>>(x, qkv_w, nullptr, nullptr, 0);

    // 2) offset convs (dil 2, 3 merged)
    offconv_kernel<<<dim3(1024, 2), 256>>>(off_w2, off_b2, off_w3, off_b3);

    // 3) deformable conv on k and v (dil 2, 3 merged)
    deform_kernel<<<dim3(1024, 2), 256, DEF_SMEM>>>(def_w2, def_b2, def_w3, def_b3);

    // 4) local attention, all 3 dilations
    attn_kernel<<<dim3(4096, 3), 256>>>();

    // 5) output projection + bias -> d_out
    sgemm_kernel<<<dim3(256, 3), 256>>>(nullptr, proj_w, proj_b, out, 1);
}

// round 8
// speedup vs baseline: 1.5323x; 1.0322x over previous
#include <cuda_runtime.h>
#include <math.h>

#define Bn 8
#define HW 4096
#define Mm 32768   // B*HW
#define HD 64

typedef unsigned long long u64;

// packed fp32x2 FMA: acc = a*b + acc (elementwise on two packed floats)
#define FFMA2(acc, a, b) \
    asm("fma.rn.f32x2 %0, %1, %2, %0;" : "+l"(acc) : "l"(a), "l"(b))

__device__ __forceinline__ u64 dup_f32(float v) {
    u64 r; asm("mov.b64 %0, {%1, %1};" : "=l"(r) : "f"(v)); return r;
}
__device__ __forceinline__ float2 u64_f2(u64 u) {
    float2 v; asm("mov.b64 {%0, %1}, %2;" : "=f"(v.x), "=f"(v.y) : "l"(u)); return v;
}

// Scratch (static device globals; no allocation allowed)
__device__ __align__(16) float g_qkv[9u * Mm * HD];   // [s*3+i][m][c]
__device__ __align__(16) float g_off[2][Mm * 18];     // offsets for dil 2,3
__device__ __align__(16) float g_defk[2][Mm * HD];    // deformed k
__device__ __align__(16) float g_defv[2][Mm * HD];    // deformed v
__device__ __align__(16) float g_attn[Mm * 192];      // attention outputs

// ---------------------------------------------------------------------------
// SGEMM: C[m,n] = sum_k A[m,k] * Bw[n,k]; 128x64 tile, 8x4 micro, k-chunk 16.
// FFMA2: accumulators packed over m-pairs; a-pairs are contiguous in As rows,
// b is duplicated per kk with mov.b64 (ALU pipe). Bitwise-identical numerics.
// mode 0: scatter into g_qkv[(n/64)][m][n%64]   (qkv projection, N=576)
// mode 1: Cout[m*192+n] = acc + bias[n], A taken from g_attn (final proj)
// ---------------------------------------------------------------------------
__global__ __launch_bounds__(256) void sgemm_kernel(
    const float* __restrict__ A, const float* __restrict__ Bw,
    const float* __restrict__ bias, float* __restrict__ Cout, int mode)
{
    __shared__ __align__(16) float As[16][132];
    __shared__ __align__(16) float Bs[16][68];
    int tid = threadIdx.x;
    int tx = tid & 15, ty = tid >> 4;    // tx: 4 n's, ty: 8 m's (4 m-pairs)
    int m0 = blockIdx.x * 128, n0 = blockIdx.y * 64;
    const float* Ap = (mode == 0) ? A : g_attn;
    u64 acc2[4][4] = {};                 // [m-pair][n]

    for (int k0 = 0; k0 < 192; k0 += 16) {
        #pragma unroll
        for (int s = 0; s < 2; s++) {
            int u = tid + s * 256;
            int mm = u >> 2, kq = u & 3;
            float4 av = *(const float4*)&Ap[(size_t)(m0 + mm) * 192 + k0 + kq * 4];
            As[kq * 4 + 0][mm] = av.x;
            As[kq * 4 + 1][mm] = av.y;
            As[kq * 4 + 2][mm] = av.z;
            As[kq * 4 + 3][mm] = av.w;
        }
        {
            int nn = tid >> 2, kq = tid & 3;
            float4 bv = *(const float4*)&Bw[(size_t)(n0 + nn) * 192 + k0 + kq * 4];
            Bs[kq * 4 + 0][nn] = bv.x;
            Bs[kq * 4 + 1][nn] = bv.y;
            Bs[kq * 4 + 2][nn] = bv.z;
            Bs[kq * 4 + 3][nn] = bv.w;
        }
        __syncthreads();
        #pragma unroll
        for (int kk = 0; kk < 16; kk++) {
            ulonglong2 a01 = *(const ulonglong2*)&As[kk][ty * 8];      // m pairs 0,1
            ulonglong2 a23 = *(const ulonglong2*)&As[kk][ty * 8 + 4];  // m pairs 2,3
            float4 b  = *(const float4*)&Bs[kk][tx * 4];
            u64 bd0 = dup_f32(b.x), bd1 = dup_f32(b.y);
            u64 bd2 = dup_f32(b.z), bd3 = dup_f32(b.w);
            FFMA2(acc2[0][0], a01.x, bd0); FFMA2(acc2[0][1], a01.x, bd1);
            FFMA2(acc2[0][2], a01.x, bd2); FFMA2(acc2[0][3], a01.x, bd3);
            FFMA2(acc2[1][0], a01.y, bd0); FFMA2(acc2[1][1], a01.y, bd1);
            FFMA2(acc2[1][2], a01.y, bd2); FFMA2(acc2[1][3], a01.y, bd3);
            FFMA2(acc2[2][0], a23.x, bd0); FFMA2(acc2[2][1], a23.x, bd1);
            FFMA2(acc2[2][2], a23.x, bd2); FFMA2(acc2[2][3], a23.x, bd3);
            FFMA2(acc2[3][0], a23.y, bd0); FFMA2(acc2[3][1], a23.y, bd1);
            FFMA2(acc2[3][2], a23.y, bd2); FFMA2(acc2[3][3], a23.y, bd3);
        }
        __syncthreads();
    }

    // unpack: m = m0 + ty*8 + (2p + half)
    if (mode == 0) {
        size_t bufbase = (size_t)blockIdx.y * Mm * 64;
        #pragma unroll
        for (int p = 0; p < 4; p++) {
            float2 c0 = u64_f2(acc2[p][0]);
            float2 c1 = u64_f2(acc2[p][1]);
            float2 c2 = u64_f2(acc2[p][2]);
            float2 c3 = u64_f2(acc2[p][3]);
            int m = m0 + ty * 8 + p * 2;
            float4 lo = {c0.x, c1.x, c2.x, c3.x};
            float4 hi = {c0.y, c1.y, c2.y, c3.y};
            *(float4*)&g_qkv[bufbase + (size_t)m * 64 + tx * 4]       = lo;
            *(float4*)&g_qkv[bufbase + (size_t)(m + 1) * 64 + tx * 4] = hi;
        }
    } else {
        float4 b4 = *(const float4*)&bias[n0 + tx * 4];
        #pragma unroll
        for (int p = 0; p < 4; p++) {
            float2 c0 = u64_f2(acc2[p][0]);
            float2 c1 = u64_f2(acc2[p][1]);
            float2 c2 = u64_f2(acc2[p][2]);
            float2 c3 = u64_f2(acc2[p][3]);
            int m = m0 + ty * 8 + p * 2;
            float4 lo = {c0.x + b4.x, c1.x + b4.y, c2.x + b4.z, c3.x + b4.w};
            float4 hi = {c0.y + b4.x, c1.y + b4.y, c2.y + b4.z, c3.y + b4.w};
            *(float4*)&Cout[(size_t)m * 192 + n0 + tx * 4]       = lo;
            *(float4*)&Cout[(size_t)(m + 1) * 192 + n0 + tx * 4] = hi;
        }
    }
}

// ---------------------------------------------------------------------------
// Offset conv: dilated 3x3 conv on k branch, 64 -> 18 ch, zero pad = dil.
// blockIdx.y selects dil (2 or 3). Block: 32 px (8 warps x 4 px),
// lanes = (px_sub 4) x (channel-octet 8). FFMA2 packed over channel pairs.
// ---------------------------------------------------------------------------
__global__ __launch_bounds__(256) void offconv_kernel(
    const float* __restrict__ ow2, const float* __restrict__ ob2,
    const float* __restrict__ ow3, const float* __restrict__ ob3)
{
    __shared__ __align__(16) float ws[18 * 612];
    int dil_idx = blockIdx.y;
    int dil = dil_idx + 2;
    const float* ow = dil_idx ? ow3 : ow2;
    const float* ob = dil_idx ? ob3 : ob2;
    const float* kin = &g_qkv[(size_t)(4 + dil_idx) * Mm * HD];
    float* offout = g_off[dil_idx];
    int tid = threadIdx.x;

    for (int i = tid; i < 18 * 576; i += 256) {
        int oc = i / 576, r = i % 576, c = r / 9, kk = r % 9;
        ws[oc * 612 + kk * 68 + c] = ow[i];
    }
    __syncthreads();

    int wr = tid >> 5, lane = tid & 31;
    int pxs = lane >> 3, cq = lane & 7;
    int m = blockIdx.x * 32 + wr * 4 + pxs;
    int b = m >> 12, hw = m & 4095, h = hw >> 6, w = hw & 63;

    u64 acc2[18] = {};

    for (int kk = 0; kk < 9; kk++) {
        int y = h + (kk / 3 - 1) * dil;
        int x = w + (kk % 3 - 1) * dil;
        ulonglong2 k0 = {0, 0}, k1 = {0, 0};
        if ((unsigned)y < 64u && (unsigned)x < 64u) {
            const float* kp = kin + (size_t)((b << 12) + (y << 6) + x) * 64 + cq * 8;
            k0 = *(const ulonglong2*)kp;
            k1 = *(const ulonglong2*)(kp + 4);
        }
        const float* wsk = ws + kk * 68 + cq * 8;
        #pragma unroll
        for (int oc = 0; oc < 18; oc++) {
            ulonglong2 w0 = *(const ulonglong2*)(wsk + oc * 612);
            ulonglong2 w1 = *(const ulonglong2*)(wsk + oc * 612 + 4);
            FFMA2(acc2[oc], k0.x, w0.x);
            FFMA2(acc2[oc], k0.y, w0.y);
            FFMA2(acc2[oc], k1.x, w1.x);
            FFMA2(acc2[oc], k1.y, w1.y);
        }
    }
    #pragma unroll
    for (int oc = 0; oc < 18; oc++) {
        float2 f = u64_f2(acc2[oc]);
        float a = f.x + f.y;
        a += __shfl_xor_sync(0xffffffffu, a, 1);
        a += __shfl_xor_sync(0xffffffffu, a, 2);
        a += __shfl_xor_sync(0xffffffffu, a, 4);
        if (cq == 0) offout[(size_t)m * 18 + oc] = a + ob[oc];
    }
}

// ---------------------------------------------------------------------------
// Deformable conv for k AND v. blockIdx.y selects dil. Block: 32 px x 64 out.
// Full sampled tile in dynamic smem, sampled ONCE with full-width LDG.128.
// GEMM FFMA2-packed over di-pairs (reduction dim); horizontal add at end.
// ---------------------------------------------------------------------------
#define S_ROW 588                 // 576 + 12 pad (16B aligned, bank-skewed)
#define DEF_SMEM (2 * 32 * S_ROW * 4 + 64 * 76 * 4 + 288 * 32)

__global__ __launch_bounds__(256) void deform_kernel(
    const float* __restrict__ dw2, const float* __restrict__ db2,
    const float* __restrict__ dw3, const float* __restrict__ db3)
{
    extern __shared__ __align__(16) float smem[];
    float*  s_k  = smem;                       // [32][S_ROW]
    float*  s_v  = smem + 32 * S_ROW;          // [32][S_ROW]
    float*  w_s  = smem + 64 * S_ROW;          // [64][76]
    int4*   s_b4 = (int4*)(w_s + 64 * 76);     // [288]
    float4* s_w4 = (float4*)(s_b4 + 288);      // [288]

    int dil_idx = blockIdx.y;
    int dil = dil_idx + 2;
    const float* dw = dil_idx ? dw3 : dw2;
    const float* db = dil_idx ? db3 : db2;
    const float* kin = &g_qkv[(size_t)(4 + dil_idx) * Mm * HD];
    const float* vin = &g_qkv[(size_t)(7 + dil_idx) * Mm * HD];
    const float* off = g_off[dil_idx];
    float* kout = g_defk[dil_idx];
    float* vout = g_defv[dil_idx];

    int tid = threadIdx.x;
    int m0 = blockIdx.x * 32;
    int bpix = m0 & ~4095;      // batch base (block within one batch)

    // ---- corner precompute: 32 px x 9 taps ----
    for (int i = tid; i < 288; i += 256) {
        int px = i / 9, kk = i % 9;
        int m = m0 + px;
        int hw = m & 4095;
        int h = hw >> 6, w = hw & 63;
        float oy = off[(size_t)m * 18 + kk * 2 + 0];
        float ox = off[(size_t)m * 18 + kk * 2 + 1];
        float py  = (float)(h + (kk / 3 - 1) * dil) + oy;
        float pxf = (float)(w + (kk % 3 - 1) * dil) + ox;
        float y0f = floorf(py), x0f = floorf(pxf);
        float wy = py - y0f, wx = pxf - x0f;
        int y0 = (int)y0f, x0 = (int)x0f;
        int yv0 = ((unsigned)y0 < 64u), yv1 = ((unsigned)(y0 + 1) < 64u);
        int xv0 = ((unsigned)x0 < 64u), xv1 = ((unsigned)(x0 + 1) < 64u);
        int4 bs;
        bs.x = (yv0 && xv0) ? ((y0 << 6) + x0)           : -1;
        bs.y = (yv0 && xv1) ? ((y0 << 6) + x0 + 1)       : -1;
        bs.z = (yv1 && xv0) ? (((y0 + 1) << 6) + x0)     : -1;
        bs.w = (yv1 && xv1) ? (((y0 + 1) << 6) + x0 + 1) : -1;
        float4 wt;
        wt.x = (1.f - wy) * (1.f - wx);
        wt.y = (1.f - wy) * wx;
        wt.z = wy * (1.f - wx);
        wt.w = wy * wx;
        s_b4[i] = bs;
        s_w4[i] = wt;
    }
    __syncthreads();

    // ---- sampling (once): warps 0-3 -> k, 4-7 -> v; 72 (px,tap) per warp ----
    {
        int warp = tid >> 5, lane = tid & 31;
        int slot = lane >> 4;             // which of 2 (px,tap) per iter
        int cq   = lane & 15;             // channel quad
        const float* src = (warp >= 4) ? vin : kin;
        float* dst = (warp >= 4) ? s_v : s_k;
        int pbase = (warp & 3) * 72;
        const float* rowbase = src + (size_t)bpix * 64 + cq * 4;
        #pragma unroll 3
        for (int s = 0; s < 36; s++) {
            int p = pbase + 2 * s + slot;
            int4 bs = s_b4[p];
            float4 wt = s_w4[p];
            int px = p / 9, kk = p - px * 9;
            float4 a = {0.f, 0.f, 0.f, 0.f};
            if (bs.x >= 0) {
                float4 v = *(const float4*)(rowbase + (size_t)bs.x * 64);
                a.x += wt.x * v.x; a.y += wt.x * v.y; a.z += wt.x * v.z; a.w += wt.x * v.w;
            }
            if (bs.y >= 0) {
                float4 v = *(const float4*)(rowbase + (size_t)bs.y * 64);
                a.x += wt.y * v.x; a.y += wt.y * v.y; a.z += wt.y * v.z; a.w += wt.y * v.w;
            }
            if (bs.z >= 0) {
                float4 v = *(const float4*)(rowbase + (size_t)bs.z * 64);
                a.x += wt.z * v.x; a.y += wt.z * v.y; a.z += wt.z * v.z; a.w += wt.z * v.w;
            }
            if (bs.w >= 0) {
                float4 v = *(const float4*)(rowbase + (size_t)bs.w * 64);
                a.x += wt.w * v.x; a.y += wt.w * v.y; a.z += wt.w * v.z; a.w += wt.w * v.w;
            }
            *(float4*)&dst[px * S_ROW + kk * 64 + cq * 4] = a;
        }
    }
    __syncthreads();

    // ---- GEMM: di = kk*64+c; thread = 2 px x 4 out x 2 tensors, FFMA2 ----
    int tx = tid & 15;          // px pair {tx, tx+16}
    int ty = tid >> 4;          // out set {ty, ty+16, ty+32, ty+48}
    u64 accK2[2][4] = {}, accV2[2][4] = {};

    for (int ch = 0; ch < 8; ch++) {
        // stage weight chunk: w_s[o][i], di = ch*72+i, dw layout [o][c][kk]
        for (int idx = tid; idx < 64 * 72; idx += 256) {
            int o = idx / 72, i = idx - o * 72;
            int di = ch * 72 + i;
            int kk = di >> 6, c = di & 63;
            w_s[o * 76 + i] = dw[o * 576 + c * 9 + kk];
        }
        __syncthreads();
        #pragma unroll 3
        for (int i = 0; i < 72; i += 4) {
            int di = ch * 72 + i;
            ulonglong2 k0 = *(const ulonglong2*)&s_k[tx * S_ROW + di];
            ulonglong2 k1 = *(const ulonglong2*)&s_k[(tx + 16) * S_ROW + di];
            ulonglong2 v0 = *(const ulonglong2*)&s_v[tx * S_ROW + di];
            ulonglong2 v1 = *(const ulonglong2*)&s_v[(tx + 16) * S_ROW + di];
            #pragma unroll
            for (int j = 0; j < 4; j++) {
                ulonglong2 wv = *(const ulonglong2*)&w_s[(ty + j * 16) * 76 + i];
                FFMA2(accK2[0][j], k0.x, wv.x); FFMA2(accK2[0][j], k0.y, wv.y);
                FFMA2(accK2[1][j], k1.x, wv.x); FFMA2(accK2[1][j], k1.y, wv.y);
                FFMA2(accV2[0][j], v0.x, wv.x); FFMA2(accV2[0][j], v0.y, wv.y);
                FFMA2(accV2[1][j], v1.x, wv.x); FFMA2(accV2[1][j], v1.y, wv.y);
            }
        }
        __syncthreads();
    }

    // horizontal add + bias
    float accK[2][4], accV[2][4];
    #pragma unroll
    for (int j = 0; j < 4; j++) {
        float bv = db[ty + j * 16];
        #pragma unroll
        for (int i = 0; i < 2; i++) {
            float2 fk = u64_f2(accK2[i][j]);
            float2 fv = u64_f2(accV2[i][j]);
            accK[i][j] = fk.x + fk.y + bv;
            accV[i][j] = fv.x + fv.y + bv;
        }
    }

    // ---- output: stage via smem (reuse s_k), coalesced STG.128 ----
    float* so = s_k;    // [32][68]
    #pragma unroll
    for (int i = 0; i < 2; i++)
        #pragma unroll
        for (int j = 0; j < 4; j++)
            so[(tx + 16 * i) * 68 + ty + 16 * j] = accK[i][j];
    __syncthreads();
    for (int idx = tid; idx < 512; idx += 256) {
        int px = idx >> 4, q = idx & 15;
        float4 val = *(const float4*)&so[px * 68 + q * 4];
        *(float4*)&kout[(size_t)(m0 + px) * 64 + q * 4] = val;
    }
    __syncthreads();
    #pragma unroll
    for (int i = 0; i < 2; i++)
        #pragma unroll
        for (int j = 0; j < 4; j++)
            so[(tx + 16 * i) * 68 + ty + 16 * j] = accV[i][j];
    __syncthreads();
    for (int idx = tid; idx < 512; idx += 256) {
        int px = idx >> 4, q = idx & 15;
        float4 val = *(const float4*)&so[px * 68 + q * 4];
        *(float4*)&vout[(size_t)(m0 + px) * 64 + q * 4] = val;
    }
}

// ---------------------------------------------------------------------------
// Attention: warp per pixel, grid (4096, 3 dilations). 9-tap softmax.
// float2-vectorized channel loads. OOB taps contribute logit EXACTLY 0.
// ---------------------------------------------------------------------------
__global__ __launch_bounds__(256) void attn_kernel()
{
    int dil_idx = blockIdx.y;
    int dil = dil_idx + 1;
    int warp = threadIdx.x >> 5, lane = threadIdx.x & 31;
    int m = blockIdx.x * 8 + warp;
    int b = m >> 12, hw = m & 4095, h = hw >> 6, w = hw & 63;
    const float* q = &g_qkv[(size_t)dil_idx * Mm * HD];
    const float *kb, *vb;
    if (dil_idx == 0) {
        kb = &g_qkv[(size_t)3 * Mm * HD];
        vb = &g_qkv[(size_t)6 * Mm * HD];
    } else {
        kb = g_defk[dil_idx - 1];
        vb = g_defv[dil_idx - 1];
    }
    float2 q01 = *(const float2*)&q[(size_t)m * 64 + lane * 2];
    float eg[9];
    int nb[9];
    float mx = -1e30f;
    #pragma unroll
    for (int j = 0; j < 9; j++) {
        int y = h + (j / 3 - 1) * dil;
        int x = w + (j % 3 - 1) * dil;
        bool valid = ((unsigned)y < 64u) && ((unsigned)x < 64u);
        float p = 0.f;
        int base = -1;
        if (valid) {
            base = (b << 12) + (y << 6) + x;
            float2 k2 = *(const float2*)&kb[(size_t)base * 64 + lane * 2];
            p = q01.x * k2.x + q01.y * k2.y;
        }
        nb[j] = base;
        #pragma unroll
        for (int s = 16; s; s >>= 1) p += __shfl_xor_sync(0xffffffffu, p, s);
        eg[j] = p * 0.125f;
        mx = fmaxf(mx, eg[j]);
    }
    float sum = 0.f;
    #pragma unroll
    for (int j = 0; j < 9; j++) { eg[j] = expf(eg[j] - mx); sum += eg[j]; }
    float inv = 1.f / sum;
    float o0 = 0.f, o1 = 0.f;
    #pragma unroll
    for (int j = 0; j < 9; j++) {
        if (nb[j] >= 0) {
            float a = eg[j] * inv;
            float2 v2 = *(const float2*)&vb[(size_t)nb[j] * 64 + lane * 2];
            o0 += a * v2.x;
            o1 += a * v2.y;
        }
    }
    float2 o = {o0, o1};
    *(float2*)&g_attn[(size_t)m * 192 + dil_idx * 64 + lane * 2] = o;
}

// ---------------------------------------------------------------------------
extern "C" void kernel_launch(void* const* d_in, const int* in_sizes, int n_in,
                              void* d_out, int out_size)
{
    const float* x      = (const float*)d_in[0];
    const float* qkv_w  = (const float*)d_in[1];
    const float* proj_w = (const float*)d_in[2];
    const float* proj_b = (const float*)d_in[3];
    const float* off_w2 = (const float*)d_in[4];
    const float* off_b2 = (const float*)d_in[5];
    const float* def_w2 = (const float*)d_in[6];
    const float* def_b2 = (const float*)d_in[7];
    const float* off_w3 = (const float*)d_in[8];
    const float* off_b3 = (const float*)d_in[9];
    const float* def_w3 = (const float*)d_in[10];
    const float* def_b3 = (const float*)d_in[11];
    float* out = (float*)d_out;

    cudaFuncSetAttribute(deform_kernel,
                         cudaFuncAttributeMaxDynamicSharedMemorySize, DEF_SMEM);

    // 1) qkv projection: (32768 x 192) @ (192 x 576) -> per-branch buffers
    sgemm_kernel<<<dim3(256, 9), 256>>>(x, qkv_w, nullptr, nullptr, 0);

    // 2) offset convs (dil 2, 3 merged)
    offconv_kernel<<<dim3(1024, 2), 256>>>(off_w2, off_b2, off_w3, off_b3);

    // 3) deformable conv on k and v (dil 2, 3 merged)
    deform_kernel<<<dim3(1024, 2), 256, DEF_SMEM>>>(def_w2, def_b2, def_w3, def_b3);

    // 4) local attention, all 3 dilations
    attn_kernel<<<dim3(4096, 3), 256>>>();

    // 5) output projection + bias -> d_out
    sgemm_kernel<<<dim3(256, 3), 256>>>(nullptr, proj_w, proj_b, out, 1);
}

// round 9
// speedup vs baseline: 1.9601x; 1.2792x over previous
#include <cuda_runtime.h>
#include <math.h>

#define Bn 8
#define HW 4096
#define Mm 32768   // B*HW
#define HD 64

typedef unsigned long long u64;

// packed fp32x2 FMA: acc = a*b + acc (elementwise on two packed floats)
#define FFMA2(acc, a, b) \
    asm("fma.rn.f32x2 %0, %1, %2, %0;" : "+l"(acc) : "l"(a), "l"(b))

__device__ __forceinline__ u64 dup_f32(float v) {
    u64 r; asm("mov.b64 %0, {%1, %1};" : "=l"(r) : "f"(v)); return r;
}
__device__ __forceinline__ float2 u64_f2(u64 u) {
    float2 v; asm("mov.b64 {%0, %1}, %2;" : "=f"(v.x), "=f"(v.y) : "l"(u)); return v;
}

// Scratch (static device globals; no allocation allowed)
__device__ __align__(16) float g_qkv[9u * Mm * HD];   // [s*3+i][m][c]
__device__ __align__(16) float g_off[2][Mm * 18];     // offsets for dil 2,3
__device__ __align__(16) float g_defk[2][Mm * HD];    // deformed k
__device__ __align__(16) float g_defv[2][Mm * HD];    // deformed v
__device__ __align__(16) float g_attn[Mm * 192];      // attention outputs
__device__ __align__(16) float g_wT[2 * 9 * 64 * 64]; // transposed def weights

// ---------------------------------------------------------------------------
// Weight transpose: g_wT[dil][kk][o][c] = dw[o][c][kk].  One-time, tiny.
// ---------------------------------------------------------------------------
__global__ void wtrans_kernel(const float* __restrict__ dw2,
                              const float* __restrict__ dw3)
{
    int idx = blockIdx.x * 256 + threadIdx.x;      // 0 .. 73727
    if (idx >= 73728) return;
    int c  = idx & 63;
    int o  = (idx >> 6) & 63;
    int kk = (idx >> 12) % 9;
    int dil = idx / 36864;
    const float* dw = dil ? dw3 : dw2;
    g_wT[idx] = dw[o * 576 + c * 9 + kk];
}

// ---------------------------------------------------------------------------
// SGEMM: C[m,n] = sum_k A[m,k] * Bw[n,k]; 128x64 tile, 8x4 micro, k-chunk 16,
// double-buffered smem, FFMA2 packed over m-pairs.
// mode 0: scatter into g_qkv[(n/64)][m][n%64]   (qkv projection, N=576)
// mode 1: Cout[m*192+n] = acc + bias[n], A taken from g_attn (final proj)
// ---------------------------------------------------------------------------
__global__ __launch_bounds__(256) void sgemm_kernel(
    const float* __restrict__ A, const float* __restrict__ Bw,
    const float* __restrict__ bias, float* __restrict__ Cout, int mode)
{
    __shared__ __align__(16) float As[2][16][132];
    __shared__ __align__(16) float Bs[2][16][68];
    int tid = threadIdx.x;
    int tx = tid & 15, ty = tid >> 4;    // tx: 4 n's, ty: 8 m's (4 m-pairs)
    int m0 = blockIdx.x * 128, n0 = blockIdx.y * 64;
    const float* Ap = (mode == 0) ? A : g_attn;
    u64 acc2[4][4] = {};                 // [m-pair][n]

    int a_m0 = tid >> 2,        a_kq0 = tid & 3;
    int a_m1 = (tid + 256) >> 2, a_kq1 = (tid + 256) & 3;
    int b_n = tid >> 2, b_kq = tid & 3;

    // stage chunk 0
    {
        float4 av0 = *(const float4*)&Ap[(size_t)(m0 + a_m0) * 192 + a_kq0 * 4];
        float4 av1 = *(const float4*)&Ap[(size_t)(m0 + a_m1) * 192 + a_kq1 * 4];
        float4 bv  = *(const float4*)&Bw[(size_t)(n0 + b_n) * 192 + b_kq * 4];
        As[0][a_kq0 * 4 + 0][a_m0] = av0.x; As[0][a_kq0 * 4 + 1][a_m0] = av0.y;
        As[0][a_kq0 * 4 + 2][a_m0] = av0.z; As[0][a_kq0 * 4 + 3][a_m0] = av0.w;
        As[0][a_kq1 * 4 + 0][a_m1] = av1.x; As[0][a_kq1 * 4 + 1][a_m1] = av1.y;
        As[0][a_kq1 * 4 + 2][a_m1] = av1.z; As[0][a_kq1 * 4 + 3][a_m1] = av1.w;
        Bs[0][b_kq * 4 + 0][b_n] = bv.x; Bs[0][b_kq * 4 + 1][b_n] = bv.y;
        Bs[0][b_kq * 4 + 2][b_n] = bv.z; Bs[0][b_kq * 4 + 3][b_n] = bv.w;
    }
    __syncthreads();

    int cur = 0;
    for (int kc = 0; kc < 12; kc++) {
        float4 pa0, pa1, pb;
        if (kc < 11) {
            int k0n = (kc + 1) * 16;
            pa0 = *(const float4*)&Ap[(size_t)(m0 + a_m0) * 192 + k0n + a_kq0 * 4];
            pa1 = *(const float4*)&Ap[(size_t)(m0 + a_m1) * 192 + k0n + a_kq1 * 4];
            pb  = *(const float4*)&Bw[(size_t)(n0 + b_n) * 192 + k0n + b_kq * 4];
        }
        #pragma unroll
        for (int kk = 0; kk < 16; kk++) {
            ulonglong2 a01 = *(const ulonglong2*)&As[cur][kk][ty * 8];
            ulonglong2 a23 = *(const ulonglong2*)&As[cur][kk][ty * 8 + 4];
            float4 b  = *(const float4*)&Bs[cur][kk][tx * 4];
            u64 bd0 = dup_f32(b.x), bd1 = dup_f32(b.y);
            u64 bd2 = dup_f32(b.z), bd3 = dup_f32(b.w);
            FFMA2(acc2[0][0], a01.x, bd0); FFMA2(acc2[0][1], a01.x, bd1);
            FFMA2(acc2[0][2], a01.x, bd2); FFMA2(acc2[0][3], a01.x, bd3);
            FFMA2(acc2[1][0], a01.y, bd0); FFMA2(acc2[1][1], a01.y, bd1);
            FFMA2(acc2[1][2], a01.y, bd2); FFMA2(acc2[1][3], a01.y, bd3);
            FFMA2(acc2[2][0], a23.x, bd0); FFMA2(acc2[2][1], a23.x, bd1);
            FFMA2(acc2[2][2], a23.x, bd2); FFMA2(acc2[2][3], a23.x, bd3);
            FFMA2(acc2[3][0], a23.y, bd0); FFMA2(acc2[3][1], a23.y, bd1);
            FFMA2(acc2[3][2], a23.y, bd2); FFMA2(acc2[3][3], a23.y, bd3);
        }
        if (kc < 11) {
            int nxt = cur ^ 1;
            As[nxt][a_kq0 * 4 + 0][a_m0] = pa0.x; As[nxt][a_kq0 * 4 + 1][a_m0] = pa0.y;
            As[nxt][a_kq0 * 4 + 2][a_m0] = pa0.z; As[nxt][a_kq0 * 4 + 3][a_m0] = pa0.w;
            As[nxt][a_kq1 * 4 + 0][a_m1] = pa1.x; As[nxt][a_kq1 * 4 + 1][a_m1] = pa1.y;
            As[nxt][a_kq1 * 4 + 2][a_m1] = pa1.z; As[nxt][a_kq1 * 4 + 3][a_m1] = pa1.w;
            Bs[nxt][b_kq * 4 + 0][b_n] = pb.x; Bs[nxt][b_kq * 4 + 1][b_n] = pb.y;
            Bs[nxt][b_kq * 4 + 2][b_n] = pb.z; Bs[nxt][b_kq * 4 + 3][b_n] = pb.w;
        }
        __syncthreads();
        cur ^= 1;
    }

    // unpack: m = m0 + ty*8 + (2p + half)
    if (mode == 0) {
        size_t bufbase = (size_t)blockIdx.y * Mm * 64;
        #pragma unroll
        for (int p = 0; p < 4; p++) {
            float2 c0 = u64_f2(acc2[p][0]);
            float2 c1 = u64_f2(acc2[p][1]);
            float2 c2 = u64_f2(acc2[p][2]);
            float2 c3 = u64_f2(acc2[p][3]);
            int m = m0 + ty * 8 + p * 2;
            float4 lo = {c0.x, c1.x, c2.x, c3.x};
            float4 hi = {c0.y, c1.y, c2.y, c3.y};
            *(float4*)&g_qkv[bufbase + (size_t)m * 64 + tx * 4]       = lo;
            *(float4*)&g_qkv[bufbase + (size_t)(m + 1) * 64 + tx * 4] = hi;
        }
    } else {
        float4 b4 = *(const float4*)&bias[n0 + tx * 4];
        #pragma unroll
        for (int p = 0; p < 4; p++) {
            float2 c0 = u64_f2(acc2[p][0]);
            float2 c1 = u64_f2(acc2[p][1]);
            float2 c2 = u64_f2(acc2[p][2]);
            float2 c3 = u64_f2(acc2[p][3]);
            int m = m0 + ty * 8 + p * 2;
            float4 lo = {c0.x + b4.x, c1.x + b4.y, c2.x + b4.z, c3.x + b4.w};
            float4 hi = {c0.y + b4.x, c1.y + b4.y, c2.y + b4.z, c3.y + b4.w};
            *(float4*)&Cout[(size_t)m * 192 + n0 + tx * 4]       = lo;
            *(float4*)&Cout[(size_t)(m + 1) * 192 + n0 + tx * 4] = hi;
        }
    }
}

// ---------------------------------------------------------------------------
// Offset conv: dilated 3x3 conv on k branch, 64 -> 18 ch, zero pad = dil.
// blockIdx.y selects dil (2 or 3). Block: 32 px (8 warps x 4 px),
// lanes = (px_sub 4) x (channel-octet 8). FFMA2 packed over channel pairs.
// ---------------------------------------------------------------------------
__global__ __launch_bounds__(256) void offconv_kernel(
    const float* __restrict__ ow2, const float* __restrict__ ob2,
    const float* __restrict__ ow3, const float* __restrict__ ob3)
{
    __shared__ __align__(16) float ws[18 * 612];
    int dil_idx = blockIdx.y;
    int dil = dil_idx + 2;
    const float* ow = dil_idx ? ow3 : ow2;
    const float* ob = dil_idx ? ob3 : ob2;
    const float* kin = &g_qkv[(size_t)(4 + dil_idx) * Mm * HD];
    float* offout = g_off[dil_idx];
    int tid = threadIdx.x;

    for (int i = tid; i < 18 * 576; i += 256) {
        int oc = i / 576, r = i % 576, c = r / 9, kk = r % 9;
        ws[oc * 612 + kk * 68 + c] = ow[i];
    }
    __syncthreads();

    int wr = tid >> 5, lane = tid & 31;
    int pxs = lane >> 3, cq = lane & 7;
    int m = blockIdx.x * 32 + wr * 4 + pxs;
    int b = m >> 12, hw = m & 4095, h = hw >> 6, w = hw & 63;

    u64 acc2[18] = {};

    for (int kk = 0; kk < 9; kk++) {
        int y = h + (kk / 3 - 1) * dil;
        int x = w + (kk % 3 - 1) * dil;
        ulonglong2 k0 = {0, 0}, k1 = {0, 0};
        if ((unsigned)y < 64u && (unsigned)x < 64u) {
            const float* kp = kin + (size_t)((b << 12) + (y << 6) + x) * 64 + cq * 8;
            k0 = *(const ulonglong2*)kp;
            k1 = *(const ulonglong2*)(kp + 4);
        }
        const float* wsk = ws + kk * 68 + cq * 8;
        #pragma unroll
        for (int oc = 0; oc < 18; oc++) {
            ulonglong2 w0 = *(const ulonglong2*)(wsk + oc * 612);
            ulonglong2 w1 = *(const ulonglong2*)(wsk + oc * 612 + 4);
            FFMA2(acc2[oc], k0.x, w0.x);
            FFMA2(acc2[oc], k0.y, w0.y);
            FFMA2(acc2[oc], k1.x, w1.x);
            FFMA2(acc2[oc], k1.y, w1.y);
        }
    }
    #pragma unroll
    for (int oc = 0; oc < 18; oc++) {
        float2 f = u64_f2(acc2[oc]);
        float a = f.x + f.y;
        a += __shfl_xor_sync(0xffffffffu, a, 1);
        a += __shfl_xor_sync(0xffffffffu, a, 2);
        a += __shfl_xor_sync(0xffffffffu, a, 4);
        if (cq == 0) offout[(size_t)m * 18 + oc] = a + ob[oc];
    }
}

// ---------------------------------------------------------------------------
// Deformable conv for k AND v, tap-chunked: 9 chunks of K=64 (one 3x3 tap
// each). Small smem (44 KB) -> 3 CTAs/SM. Sampling per chunk uses full-row
// LDG.128 (each (px,tap) sampled exactly once overall). Weights come from
// pre-transposed g_wT (coalesced). GEMM: thread = 2px x 4out x 2tensors,
// FFMA2 over channel pairs.
// ---------------------------------------------------------------------------
__global__ __launch_bounds__(256) void deform_kernel(
    const float* __restrict__ db2, const float* __restrict__ db3)
{
    __shared__ __align__(16) float s_k[32][68];
    __shared__ __align__(16) float s_v[32][68];
    __shared__ __align__(16) float w_s[64][68];
    __shared__ __align__(16) int4   s_b4[288];   // [kk*32 + px]
    __shared__ __align__(16) float4 s_w4[288];

    int dil_idx = blockIdx.y;
    int dil = dil_idx + 2;
    const float* db = dil_idx ? db3 : db2;
    const float* kin = &g_qkv[(size_t)(4 + dil_idx) * Mm * HD];
    const float* vin = &g_qkv[(size_t)(7 + dil_idx) * Mm * HD];
    const float* off = g_off[dil_idx];
    float* kout = g_defk[dil_idx];
    float* vout = g_defv[dil_idx];

    int tid = threadIdx.x;
    int m0 = blockIdx.x * 32;
    int bpix = m0 & ~4095;      // batch base (block within one batch)

    // ---- corner precompute: all 9 taps x 32 px ----
    for (int i = tid; i < 288; i += 256) {
        int px = i & 31, kk = i >> 5;
        int m = m0 + px;
        int hw = m & 4095;
        int h = hw >> 6, w = hw & 63;
        float oy = off[(size_t)m * 18 + kk * 2 + 0];
        float ox = off[(size_t)m * 18 + kk * 2 + 1];
        float py  = (float)(h + (kk / 3 - 1) * dil) + oy;
        float pxf = (float)(w + (kk % 3 - 1) * dil) + ox;
        float y0f = floorf(py), x0f = floorf(pxf);
        float wy = py - y0f, wx = pxf - x0f;
        int y0 = (int)y0f, x0 = (int)x0f;
        int yv0 = ((unsigned)y0 < 64u), yv1 = ((unsigned)(y0 + 1) < 64u);
        int xv0 = ((unsigned)x0 < 64u), xv1 = ((unsigned)(x0 + 1) < 64u);
        int4 bs;
        bs.x = (yv0 && xv0) ? ((y0 << 6) + x0)           : -1;
        bs.y = (yv0 && xv1) ? ((y0 << 6) + x0 + 1)       : -1;
        bs.z = (yv1 && xv0) ? (((y0 + 1) << 6) + x0)     : -1;
        bs.w = (yv1 && xv1) ? (((y0 + 1) << 6) + x0 + 1) : -1;
        float4 wt;
        wt.x = (1.f - wy) * (1.f - wx);
        wt.y = (1.f - wy) * wx;
        wt.z = wy * (1.f - wx);
        wt.w = wy * wx;
        s_b4[kk * 32 + px] = bs;
        s_w4[kk * 32 + px] = wt;
    }
    __syncthreads();

    int tx = tid & 15;          // px pair {tx, tx+16}
    int ty = tid >> 4;          // out set {ty, ty+16, ty+32, ty+48}
    int warp = tid >> 5, lane = tid & 31;
    int slot = lane >> 4, cq = lane & 15;

    u64 accK2[2][4] = {}, accV2[2][4] = {};

    for (int kk = 0; kk < 9; kk++) {
        // sample this tap: 64 tasks (tensor x px), 8 per warp
        #pragma unroll
        for (int it = 0; it < 4; it++) {
            int t = warp * 8 + it * 2 + slot;
            int tens = t >> 5, px = t & 31;
            const float* src = tens ? vin : kin;
            float* dst = tens ? &s_v[px][0] : &s_k[px][0];
            int4 bs = s_b4[kk * 32 + px];
            float4 wt = s_w4[kk * 32 + px];
            const float* rowbase = src + (size_t)bpix * 64 + cq * 4;
            float4 a = {0.f, 0.f, 0.f, 0.f};
            if (bs.x >= 0) {
                float4 v = *(const float4*)(rowbase + (size_t)bs.x * 64);
                a.x += wt.x * v.x; a.y += wt.x * v.y; a.z += wt.x * v.z; a.w += wt.x * v.w;
            }
            if (bs.y >= 0) {
                float4 v = *(const float4*)(rowbase + (size_t)bs.y * 64);
                a.x += wt.y * v.x; a.y += wt.y * v.y; a.z += wt.y * v.z; a.w += wt.y * v.w;
            }
            if (bs.z >= 0) {
                float4 v = *(const float4*)(rowbase + (size_t)bs.z * 64);
                a.x += wt.z * v.x; a.y += wt.z * v.y; a.z += wt.z * v.z; a.w += wt.z * v.w;
            }
            if (bs.w >= 0) {
                float4 v = *(const float4*)(rowbase + (size_t)bs.w * 64);
                a.x += wt.w * v.x; a.y += wt.w * v.y; a.z += wt.w * v.z; a.w += wt.w * v.w;
            }
            *(float4*)&dst[cq * 4] = a;
        }
        // stage weights for this tap (coalesced from g_wT)
        {
            const float* wsrc = &g_wT[(size_t)(dil_idx * 9 + kk) * 4096];
            for (int idx = tid; idx < 1024; idx += 256) {
                int o = idx >> 4, q = idx & 15;
                *(float4*)&w_s[o][q * 4] = *(const float4*)&wsrc[o * 64 + q * 4];
            }
        }
        __syncthreads();

        // GEMM over 64 channels of this tap
        #pragma unroll
        for (int c = 0; c < 64; c += 4) {
            ulonglong2 k0 = *(const ulonglong2*)&s_k[tx][c];
            ulonglong2 k1 = *(const ulonglong2*)&s_k[tx + 16][c];
            ulonglong2 v0 = *(const ulonglong2*)&s_v[tx][c];
            ulonglong2 v1 = *(const ulonglong2*)&s_v[tx + 16][c];
            #pragma unroll
            for (int j = 0; j < 4; j++) {
                ulonglong2 wv = *(const ulonglong2*)&w_s[ty + j * 16][c];
                FFMA2(accK2[0][j], k0.x, wv.x); FFMA2(accK2[0][j], k0.y, wv.y);
                FFMA2(accK2[1][j], k1.x, wv.x); FFMA2(accK2[1][j], k1.y, wv.y);
                FFMA2(accV2[0][j], v0.x, wv.x); FFMA2(accV2[0][j], v0.y, wv.y);
                FFMA2(accV2[1][j], v1.x, wv.x); FFMA2(accV2[1][j], v1.y, wv.y);
            }
        }
        __syncthreads();
    }

    // horizontal add + bias
    float accK[2][4], accV[2][4];
    #pragma unroll
    for (int j = 0; j < 4; j++) {
        float bv = db[ty + j * 16];
        #pragma unroll
        for (int i = 0; i < 2; i++) {
            float2 fk = u64_f2(accK2[i][j]);
            float2 fv = u64_f2(accV2[i][j]);
            accK[i][j] = fk.x + fk.y + bv;
            accV[i][j] = fv.x + fv.y + bv;
        }
    }

    // ---- output: stage via smem (reuse s_k), coalesced STG.128 ----
    float* so = &s_k[0][0];    // [32][68]
    #pragma unroll
    for (int i = 0; i < 2; i++)
        #pragma unroll
        for (int j = 0; j < 4; j++)
            so[(tx + 16 * i) * 68 + ty + 16 * j] = accK[i][j];
    __syncthreads();
    for (int idx = tid; idx < 512; idx += 256) {
        int px = idx >> 4, q = idx & 15;
        float4 val = *(const float4*)&so[px * 68 + q * 4];
        *(float4*)&kout[(size_t)(m0 + px) * 64 + q * 4] = val;
    }
    __syncthreads();
    #pragma unroll
    for (int i = 0; i < 2; i++)
        #pragma unroll
        for (int j = 0; j < 4; j++)
            so[(tx + 16 * i) * 68 + ty + 16 * j] = accV[i][j];
    __syncthreads();
    for (int idx = tid; idx < 512; idx += 256) {
        int px = idx >> 4, q = idx & 15;
        float4 val = *(const float4*)&so[px * 68 + q * 4];
        *(float4*)&vout[(size_t)(m0 + px) * 64 + q * 4] = val;
    }
}

// ---------------------------------------------------------------------------
// Attention: warp per pixel, grid (4096, 3 dilations). 9-tap softmax.
// float2-vectorized channel loads. OOB taps contribute logit EXACTLY 0.
// ---------------------------------------------------------------------------
__global__ __launch_bounds__(256) void attn_kernel()
{
    int dil_idx = blockIdx.y;
    int dil = dil_idx + 1;
    int warp = threadIdx.x >> 5, lane = threadIdx.x & 31;
    int m = blockIdx.x * 8 + warp;
    int b = m >> 12, hw = m & 4095, h = hw >> 6, w = hw & 63;
    const float* q = &g_qkv[(size_t)dil_idx * Mm * HD];
    const float *kb, *vb;
    if (dil_idx == 0) {
        kb = &g_qkv[(size_t)3 * Mm * HD];
        vb = &g_qkv[(size_t)6 * Mm * HD];
    } else {
        kb = g_defk[dil_idx - 1];
        vb = g_defv[dil_idx - 1];
    }
    float2 q01 = *(const float2*)&q[(size_t)m * 64 + lane * 2];
    float eg[9];
    int nb[9];
    float mx = -1e30f;
    #pragma unroll
    for (int j = 0; j < 9; j++) {
        int y = h + (j / 3 - 1) * dil;
        int x = w + (j % 3 - 1) * dil;
        bool valid = ((unsigned)y < 64u) && ((unsigned)x < 64u);
        float p = 0.f;
        int base = -1;
        if (valid) {
            base = (b << 12) + (y << 6) + x;
            float2 k2 = *(const float2*)&kb[(size_t)base * 64 + lane * 2];
            p = q01.x * k2.x + q01.y * k2.y;
        }
        nb[j] = base;
        #pragma unroll
        for (int s = 16; s; s >>= 1) p += __shfl_xor_sync(0xffffffffu, p, s);
        eg[j] = p * 0.125f;
        mx = fmaxf(mx, eg[j]);
    }
    float sum = 0.f;
    #pragma unroll
    for (int j = 0; j < 9; j++) { eg[j] = expf(eg[j] - mx); sum += eg[j]; }
    float inv = 1.f / sum;
    float o0 = 0.f, o1 = 0.f;
    #pragma unroll
    for (int j = 0; j < 9; j++) {
        if (nb[j] >= 0) {
            float a = eg[j] * inv;
            float2 v2 = *(const float2*)&vb[(size_t)nb[j] * 64 + lane * 2];
            o0 += a * v2.x;
            o1 += a * v2.y;
        }
    }
    float2 o = {o0, o1};
    *(float2*)&g_attn[(size_t)m * 192 + dil_idx * 64 + lane * 2] = o;
}

// ---------------------------------------------------------------------------
extern "C" void kernel_launch(void* const* d_in, const int* in_sizes, int n_in,
                              void* d_out, int out_size)
{
    const float* x      = (const float*)d_in[0];
    const float* qkv_w  = (const float*)d_in[1];
    const float* proj_w = (const float*)d_in[2];
    const float* proj_b = (const float*)d_in[3];
    const float* off_w2 = (const float*)d_in[4];
    const float* off_b2 = (const float*)d_in[5];
    const float* def_w2 = (const float*)d_in[6];
    const float* def_b2 = (const float*)d_in[7];
    const float* off_w3 = (const float*)d_in[8];
    const float* off_b3 = (const float*)d_in[9];
    const float* def_w3 = (const float*)d_in[10];
    const float* def_b3 = (const float*)d_in[11];
    float* out = (float*)d_out;

    // 0) one-time deform-weight transpose (tiny)
    wtrans_kernel<<<288, 256>>>(def_w2, def_w3);

    // 1) qkv projection: (32768 x 192) @ (192 x 576) -> per-branch buffers
    sgemm_kernel<<<dim3(256, 9), 256>>>(x, qkv_w, nullptr, nullptr, 0);

    // 2) offset convs (dil 2, 3 merged)
    offconv_kernel<<<dim3(1024, 2), 256>>>(off_w2, off_b2, off_w3, off_b3);

    // 3) deformable conv on k and v (dil 2, 3 merged)
    deform_kernel<<<dim3(1024, 2), 256>>>(def_b2, def_b3);

    // 4) local attention, all 3 dilations
    attn_kernel<<<dim3(4096, 3), 256>>>();

    // 5) output projection + bias -> d_out
    sgemm_kernel<<<dim3(256, 3), 256>>>(nullptr, proj_w, proj_b, out, 1);
}

// round 10
// speedup vs baseline: 2.1366x; 1.0901x over previous
#include <cuda_runtime.h>
#include <math.h>

#define Bn 8
#define HW 4096
#define Mm 32768   // B*HW
#define HD 64

typedef unsigned long long u64;

// packed fp32x2 FMA: acc = a*b + acc (elementwise on two packed floats)
#define FFMA2(acc, a, b) \
    asm("fma.rn.f32x2 %0, %1, %2, %0;" : "+l"(acc) : "l"(a), "l"(b))

__device__ __forceinline__ u64 dup_f32(float v) {
    u64 r; asm("mov.b64 %0, {%1, %1};" : "=l"(r) : "f"(v)); return r;
}
__device__ __forceinline__ float2 u64_f2(u64 u) {
    float2 v; asm("mov.b64 {%0, %1}, %2;" : "=f"(v.x), "=f"(v.y) : "l"(u)); return v;
}

// Scratch (static device globals; no allocation allowed)
__device__ __align__(16) float g_qkv[9u * Mm * HD];   // [s*3+i][m][c]
__device__ __align__(16) float g_off[2][Mm * 18];     // offsets for dil 2,3
__device__ __align__(16) float g_defk[2][Mm * HD];    // deformed k
__device__ __align__(16) float g_defv[2][Mm * HD];    // deformed v
__device__ __align__(16) float g_attn[Mm * 192];      // attention outputs
__device__ __align__(16) float g_wT[2 * 9 * 64 * 64]; // transposed def weights

// ---------------------------------------------------------------------------
// Weight transpose: g_wT[dil][kk][o][c] = dw[o][c][kk].  One-time, tiny.
// ---------------------------------------------------------------------------
__global__ void wtrans_kernel(const float* __restrict__ dw2,
                              const float* __restrict__ dw3)
{
    int idx = blockIdx.x * 256 + threadIdx.x;      // 0 .. 73727
    if (idx >= 73728) return;
    int c  = idx & 63;
    int o  = (idx >> 6) & 63;
    int kk = (idx >> 12) % 9;
    int dil = idx / 36864;
    const float* dw = dil ? dw3 : dw2;
    g_wT[idx] = dw[o * 576 + c * 9 + kk];
}

// ---------------------------------------------------------------------------
// SGEMM: C[m,n] = sum_k A[m,k] * Bw[n,k]; 128x64 tile, 8x4 micro, k-chunk 16,
// double-buffered smem, FFMA2 packed over m-pairs.
// mode 0: scatter into g_qkv[(n/64)][m][n%64]   (qkv projection, N=576)
// mode 1: Cout[m*192+n] = acc + bias[n], A taken from g_attn (final proj)
// ---------------------------------------------------------------------------
__global__ __launch_bounds__(256) void sgemm_kernel(
    const float* __restrict__ A, const float* __restrict__ Bw,
    const float* __restrict__ bias, float* __restrict__ Cout, int mode)
{
    __shared__ __align__(16) float As[2][16][132];
    __shared__ __align__(16) float Bs[2][16][68];
    int tid = threadIdx.x;
    int tx = tid & 15, ty = tid >> 4;    // tx: 4 n's, ty: 8 m's (4 m-pairs)
    int m0 = blockIdx.x * 128, n0 = blockIdx.y * 64;
    const float* Ap = (mode == 0) ? A : g_attn;
    u64 acc2[4][4] = {};                 // [m-pair][n]

    int a_m0 = tid >> 2,        a_kq0 = tid & 3;
    int a_m1 = (tid + 256) >> 2, a_kq1 = (tid + 256) & 3;
    int b_n = tid >> 2, b_kq = tid & 3;

    // stage chunk 0
    {
        float4 av0 = *(const float4*)&Ap[(size_t)(m0 + a_m0) * 192 + a_kq0 * 4];
        float4 av1 = *(const float4*)&Ap[(size_t)(m0 + a_m1) * 192 + a_kq1 * 4];
        float4 bv  = *(const float4*)&Bw[(size_t)(n0 + b_n) * 192 + b_kq * 4];
        As[0][a_kq0 * 4 + 0][a_m0] = av0.x; As[0][a_kq0 * 4 + 1][a_m0] = av0.y;
        As[0][a_kq0 * 4 + 2][a_m0] = av0.z; As[0][a_kq0 * 4 + 3][a_m0] = av0.w;
        As[0][a_kq1 * 4 + 0][a_m1] = av1.x; As[0][a_kq1 * 4 + 1][a_m1] = av1.y;
        As[0][a_kq1 * 4 + 2][a_m1] = av1.z; As[0][a_kq1 * 4 + 3][a_m1] = av1.w;
        Bs[0][b_kq * 4 + 0][b_n] = bv.x; Bs[0][b_kq * 4 + 1][b_n] = bv.y;
        Bs[0][b_kq * 4 + 2][b_n] = bv.z; Bs[0][b_kq * 4 + 3][b_n] = bv.w;
    }
    __syncthreads();

    int cur = 0;
    for (int kc = 0; kc < 12; kc++) {
        float4 pa0, pa1, pb;
        if (kc < 11) {
            int k0n = (kc + 1) * 16;
            pa0 = *(const float4*)&Ap[(size_t)(m0 + a_m0) * 192 + k0n + a_kq0 * 4];
            pa1 = *(const float4*)&Ap[(size_t)(m0 + a_m1) * 192 + k0n + a_kq1 * 4];
            pb  = *(const float4*)&Bw[(size_t)(n0 + b_n) * 192 + k0n + b_kq * 4];
        }
        #pragma unroll
        for (int kk = 0; kk < 16; kk++) {
            ulonglong2 a01 = *(const ulonglong2*)&As[cur][kk][ty * 8];
            ulonglong2 a23 = *(const ulonglong2*)&As[cur][kk][ty * 8 + 4];
            float4 b  = *(const float4*)&Bs[cur][kk][tx * 4];
            u64 bd0 = dup_f32(b.x), bd1 = dup_f32(b.y);
            u64 bd2 = dup_f32(b.z), bd3 = dup_f32(b.w);
            FFMA2(acc2[0][0], a01.x, bd0); FFMA2(acc2[0][1], a01.x, bd1);
            FFMA2(acc2[0][2], a01.x, bd2); FFMA2(acc2[0][3], a01.x, bd3);
            FFMA2(acc2[1][0], a01.y, bd0); FFMA2(acc2[1][1], a01.y, bd1);
            FFMA2(acc2[1][2], a01.y, bd2); FFMA2(acc2[1][3], a01.y, bd3);
            FFMA2(acc2[2][0], a23.x, bd0); FFMA2(acc2[2][1], a23.x, bd1);
            FFMA2(acc2[2][2], a23.x, bd2); FFMA2(acc2[2][3], a23.x, bd3);
            FFMA2(acc2[3][0], a23.y, bd0); FFMA2(acc2[3][1], a23.y, bd1);
            FFMA2(acc2[3][2], a23.y, bd2); FFMA2(acc2[3][3], a23.y, bd3);
        }
        if (kc < 11) {
            int nxt = cur ^ 1;
            As[nxt][a_kq0 * 4 + 0][a_m0] = pa0.x; As[nxt][a_kq0 * 4 + 1][a_m0] = pa0.y;
            As[nxt][a_kq0 * 4 + 2][a_m0] = pa0.z; As[nxt][a_kq0 * 4 + 3][a_m0] = pa0.w;
            As[nxt][a_kq1 * 4 + 0][a_m1] = pa1.x; As[nxt][a_kq1 * 4 + 1][a_m1] = pa1.y;
            As[nxt][a_kq1 * 4 + 2][a_m1] = pa1.z; As[nxt][a_kq1 * 4 + 3][a_m1] = pa1.w;
            Bs[nxt][b_kq * 4 + 0][b_n] = pb.x; Bs[nxt][b_kq * 4 + 1][b_n] = pb.y;
            Bs[nxt][b_kq * 4 + 2][b_n] = pb.z; Bs[nxt][b_kq * 4 + 3][b_n] = pb.w;
        }
        __syncthreads();
        cur ^= 1;
    }

    // unpack: m = m0 + ty*8 + (2p + half)
    if (mode == 0) {
        size_t bufbase = (size_t)blockIdx.y * Mm * 64;
        #pragma unroll
        for (int p = 0; p < 4; p++) {
            float2 c0 = u64_f2(acc2[p][0]);
            float2 c1 = u64_f2(acc2[p][1]);
            float2 c2 = u64_f2(acc2[p][2]);
            float2 c3 = u64_f2(acc2[p][3]);
            int m = m0 + ty * 8 + p * 2;
            float4 lo = {c0.x, c1.x, c2.x, c3.x};
            float4 hi = {c0.y, c1.y, c2.y, c3.y};
            *(float4*)&g_qkv[bufbase + (size_t)m * 64 + tx * 4]       = lo;
            *(float4*)&g_qkv[bufbase + (size_t)(m + 1) * 64 + tx * 4] = hi;
        }
    } else {
        float4 b4 = *(const float4*)&bias[n0 + tx * 4];
        #pragma unroll
        for (int p = 0; p < 4; p++) {
            float2 c0 = u64_f2(acc2[p][0]);
            float2 c1 = u64_f2(acc2[p][1]);
            float2 c2 = u64_f2(acc2[p][2]);
            float2 c3 = u64_f2(acc2[p][3]);
            int m = m0 + ty * 8 + p * 2;
            float4 lo = {c0.x + b4.x, c1.x + b4.y, c2.x + b4.z, c3.x + b4.w};
            float4 hi = {c0.y + b4.x, c1.y + b4.y, c2.y + b4.z, c3.y + b4.w};
            *(float4*)&Cout[(size_t)m * 192 + n0 + tx * 4]       = lo;
            *(float4*)&Cout[(size_t)(m + 1) * 192 + n0 + tx * 4] = hi;
        }
    }
}

// ---------------------------------------------------------------------------
// Offset conv: dilated 3x3 conv on k branch, 64 -> 18 ch, zero pad = dil.
// blockIdx.y selects dil (2 or 3). Block: 32 px (8 warps x 4 px),
// lanes = (px_sub 4) x (channel-octet 8). FFMA2 packed over channel pairs.
// ---------------------------------------------------------------------------
__global__ __launch_bounds__(256) void offconv_kernel(
    const float* __restrict__ ow2, const float* __restrict__ ob2,
    const float* __restrict__ ow3, const float* __restrict__ ob3)
{
    __shared__ __align__(16) float ws[18 * 612];
    int dil_idx = blockIdx.y;
    int dil = dil_idx + 2;
    const float* ow = dil_idx ? ow3 : ow2;
    const float* ob = dil_idx ? ob3 : ob2;
    const float* kin = &g_qkv[(size_t)(4 + dil_idx) * Mm * HD];
    float* offout = g_off[dil_idx];
    int tid = threadIdx.x;

    for (int i = tid; i < 18 * 576; i += 256) {
        int oc = i / 576, r = i % 576, c = r / 9, kk = r % 9;
        ws[oc * 612 + kk * 68 + c] = ow[i];
    }
    __syncthreads();

    int wr = tid >> 5, lane = tid & 31;
    int pxs = lane >> 3, cq = lane & 7;
    int m = blockIdx.x * 32 + wr * 4 + pxs;
    int b = m >> 12, hw = m & 4095, h = hw >> 6, w = hw & 63;

    u64 acc2[18] = {};

    for (int kk = 0; kk < 9; kk++) {
        int y = h + (kk / 3 - 1) * dil;
        int x = w + (kk % 3 - 1) * dil;
        ulonglong2 k0 = {0, 0}, k1 = {0, 0};
        if ((unsigned)y < 64u && (unsigned)x < 64u) {
            const float* kp = kin + (size_t)((b << 12) + (y << 6) + x) * 64 + cq * 8;
            k0 = *(const ulonglong2*)kp;
            k1 = *(const ulonglong2*)(kp + 4);
        }
        const float* wsk = ws + kk * 68 + cq * 8;
        #pragma unroll
        for (int oc = 0; oc < 18; oc++) {
            ulonglong2 w0 = *(const ulonglong2*)(wsk + oc * 612);
            ulonglong2 w1 = *(const ulonglong2*)(wsk + oc * 612 + 4);
            FFMA2(acc2[oc], k0.x, w0.x);
            FFMA2(acc2[oc], k0.y, w0.y);
            FFMA2(acc2[oc], k1.x, w1.x);
            FFMA2(acc2[oc], k1.y, w1.y);
        }
    }
    #pragma unroll
    for (int oc = 0; oc < 18; oc++) {
        float2 f = u64_f2(acc2[oc]);
        float a = f.x + f.y;
        a += __shfl_xor_sync(0xffffffffu, a, 1);
        a += __shfl_xor_sync(0xffffffffu, a, 2);
        a += __shfl_xor_sync(0xffffffffu, a, 4);
        if (cq == 0) offout[(size_t)m * 18 + oc] = a + ob[oc];
    }
}

// ---------------------------------------------------------------------------
// Deformable conv for k AND v, tap-chunked AND software-pipelined: while the
// GEMM consumes tap kk from smem stage kk&1, the sample-LDGs and weight-LDGs
// for tap kk+1 are already in flight (results parked in registers, stored to
// the other stage after the GEMM). One barrier per tap.
// ---------------------------------------------------------------------------
__global__ __launch_bounds__(256, 2) void deform_kernel(
    const float* __restrict__ db2, const float* __restrict__ db3)
{
    __shared__ __align__(16) float s_k[2][32][68];
    __shared__ __align__(16) float s_v[2][32][68];
    __shared__ __align__(16) float w_s[2][64][68];
    __shared__ __align__(16) int4   s_b4[288];   // [kk*32 + px]
    __shared__ __align__(16) float4 s_w4[288];

    int dil_idx = blockIdx.y;
    int dil = dil_idx + 2;
    const float* db = dil_idx ? db3 : db2;
    const float* kin = &g_qkv[(size_t)(4 + dil_idx) * Mm * HD];
    const float* vin = &g_qkv[(size_t)(7 + dil_idx) * Mm * HD];
    const float* off = g_off[dil_idx];
    float* kout = g_defk[dil_idx];
    float* vout = g_defv[dil_idx];

    int tid = threadIdx.x;
    int m0 = blockIdx.x * 32;
    int bpix = m0 & ~4095;      // batch base (block within one batch)

    // ---- corner precompute: all 9 taps x 32 px ----
    for (int i = tid; i < 288; i += 256) {
        int px = i & 31, kk = i >> 5;
        int m = m0 + px;
        int hw = m & 4095;
        int h = hw >> 6, w = hw & 63;
        float oy = off[(size_t)m * 18 + kk * 2 + 0];
        float ox = off[(size_t)m * 18 + kk * 2 + 1];
        float py  = (float)(h + (kk / 3 - 1) * dil) + oy;
        float pxf = (float)(w + (kk % 3 - 1) * dil) + ox;
        float y0f = floorf(py), x0f = floorf(pxf);
        float wy = py - y0f, wx = pxf - x0f;
        int y0 = (int)y0f, x0 = (int)x0f;
        int yv0 = ((unsigned)y0 < 64u), yv1 = ((unsigned)(y0 + 1) < 64u);
        int xv0 = ((unsigned)x0 < 64u), xv1 = ((unsigned)(x0 + 1) < 64u);
        int4 bs;
        bs.x = (yv0 && xv0) ? ((y0 << 6) + x0)           : -1;
        bs.y = (yv0 && xv1) ? ((y0 << 6) + x0 + 1)       : -1;
        bs.z = (yv1 && xv0) ? (((y0 + 1) << 6) + x0)     : -1;
        bs.w = (yv1 && xv1) ? (((y0 + 1) << 6) + x0 + 1) : -1;
        float4 wt;
        wt.x = (1.f - wy) * (1.f - wx);
        wt.y = (1.f - wy) * wx;
        wt.z = wy * (1.f - wx);
        wt.w = wy * wx;
        s_b4[kk * 32 + px] = bs;
        s_w4[kk * 32 + px] = wt;
    }
    __syncthreads();

    int tx = tid & 15;          // px pair {tx, tx+16}
    int ty = tid >> 4;          // out set {ty, ty+16, ty+32, ty+48}
    int warp = tid >> 5, lane = tid & 31;
    int slot = lane >> 4, cq = lane & 15;
    int tens = warp >= 4;
    const float* srcT = tens ? vin : kin;
    const float* rowbase = srcT + (size_t)bpix * 64 + cq * 4;
    const float* wbase = &g_wT[(size_t)dil_idx * 9 * 4096];
    int w_o = tid >> 4, w_q = tid & 15;     // weight-staging role (4 rows apart)

    float4 sm[4];       // sampled values in flight
    float4 wrg[4];      // weight values in flight

#define SAMPLE_TAP(KK)                                                        \
    do {                                                                      \
        _Pragma("unroll")                                                     \
        for (int it = 0; it < 4; it++) {                                      \
            int px = (warp * 8 + it * 2 + slot) & 31;                         \
            int4 bs = s_b4[(KK) * 32 + px];                                   \
            float4 wt = s_w4[(KK) * 32 + px];                                 \
            float4 a = {0.f, 0.f, 0.f, 0.f};                                  \
            if (bs.x >= 0) {                                                  \
                float4 v = *(const float4*)(rowbase + (size_t)bs.x * 64);     \
                a.x += wt.x * v.x; a.y += wt.x * v.y;                         \
                a.z += wt.x * v.z; a.w += wt.x * v.w;                         \
            }                                                                 \
            if (bs.y >= 0) {                                                  \
                float4 v = *(const float4*)(rowbase + (size_t)bs.y * 64);     \
                a.x += wt.y * v.x; a.y += wt.y * v.y;                         \
                a.z += wt.y * v.z; a.w += wt.y * v.w;                         \
            }                                                                 \
            if (bs.z >= 0) {                                                  \
                float4 v = *(const float4*)(rowbase + (size_t)bs.z * 64);     \
                a.x += wt.z * v.x; a.y += wt.z * v.y;                         \
                a.z += wt.z * v.z; a.w += wt.z * v.w;                         \
            }                                                                 \
            if (bs.w >= 0) {                                                  \
                float4 v = *(const float4*)(rowbase + (size_t)bs.w * 64);     \
                a.x += wt.w * v.x; a.y += wt.w * v.y;                         \
                a.z += wt.w * v.z; a.w += wt.w * v.w;                         \
            }                                                                 \
            sm[it] = a;                                                       \
        }                                                                     \
    } while (0)

#define STORE_TAP(BUF)                                                        \
    do {                                                                      \
        _Pragma("unroll")                                                     \
        for (int it = 0; it < 4; it++) {                                      \
            int px = (warp * 8 + it * 2 + slot) & 31;                         \
            float* dst = tens ? &s_v[BUF][px][0] : &s_k[BUF][px][0];          \
            *(float4*)&dst[cq * 4] = sm[it];                                  \
        }                                                                     \
    } while (0)

#define LOAD_W(KK)                                                            \
    do {                                                                      \
        const float* wsrc = wbase + (KK) * 4096;                              \
        _Pragma("unroll")                                                     \
        for (int i = 0; i < 4; i++)                                           \
            wrg[i] = *(const float4*)&wsrc[(w_o + i * 16) * 64 + w_q * 4];    \
    } while (0)

#define STORE_W(BUF)                                                          \
    do {                                                                      \
        _Pragma("unroll")                                                     \
        for (int i = 0; i < 4; i++)                                           \
            *(float4*)&w_s[BUF][w_o + i * 16][w_q * 4] = wrg[i];              \
    } while (0)

    u64 accK2[2][4] = {}, accV2[2][4] = {};

    // prologue: tap 0 into stage 0
    SAMPLE_TAP(0);
    LOAD_W(0);
    STORE_TAP(0);
    STORE_W(0);
    __syncthreads();

    for (int kk = 0; kk < 9; kk++) {
        int cur = kk & 1;
        if (kk < 8) {           // launch next tap's loads (hidden by GEMM)
            SAMPLE_TAP(kk + 1);
            LOAD_W(kk + 1);
        }
        // GEMM over 64 channels of tap kk
        #pragma unroll
        for (int c = 0; c < 64; c += 4) {
            ulonglong2 k0 = *(const ulonglong2*)&s_k[cur][tx][c];
            ulonglong2 k1 = *(const ulonglong2*)&s_k[cur][tx + 16][c];
            ulonglong2 v0 = *(const ulonglong2*)&s_v[cur][tx][c];
            ulonglong2 v1 = *(const ulonglong2*)&s_v[cur][tx + 16][c];
            #pragma unroll
            for (int j = 0; j < 4; j++) {
                ulonglong2 wv = *(const ulonglong2*)&w_s[cur][ty + j * 16][c];
                FFMA2(accK2[0][j], k0.x, wv.x); FFMA2(accK2[0][j], k0.y, wv.y);
                FFMA2(accK2[1][j], k1.x, wv.x); FFMA2(accK2[1][j], k1.y, wv.y);
                FFMA2(accV2[0][j], v0.x, wv.x); FFMA2(accV2[0][j], v0.y, wv.y);
                FFMA2(accV2[1][j], v1.x, wv.x); FFMA2(accV2[1][j], v1.y, wv.y);
            }
        }
        if (kk < 8) {
            STORE_TAP(cur ^ 1);
            STORE_W(cur ^ 1);
        }
        __syncthreads();
    }

    // horizontal add + bias
    float accK[2][4], accV[2][4];
    #pragma unroll
    for (int j = 0; j < 4; j++) {
        float bv = db[ty + j * 16];
        #pragma unroll
        for (int i = 0; i < 2; i++) {
            float2 fk = u64_f2(accK2[i][j]);
            float2 fv = u64_f2(accV2[i][j]);
            accK[i][j] = fk.x + fk.y + bv;
            accV[i][j] = fv.x + fv.y + bv;
        }
    }

    // ---- output: stage via smem (reuse s_k), coalesced STG.128 ----
    float* so = &s_k[0][0][0];    // [32][68]
    #pragma unroll
    for (int i = 0; i < 2; i++)
        #pragma unroll
        for (int j = 0; j < 4; j++)
            so[(tx + 16 * i) * 68 + ty + 16 * j] = accK[i][j];
    __syncthreads();
    for (int idx = tid; idx < 512; idx += 256) {
        int px = idx >> 4, q = idx & 15;
        float4 val = *(const float4*)&so[px * 68 + q * 4];
        *(float4*)&kout[(size_t)(m0 + px) * 64 + q * 4] = val;
    }
    __syncthreads();
    #pragma unroll
    for (int i = 0; i < 2; i++)
        #pragma unroll
        for (int j = 0; j < 4; j++)
            so[(tx + 16 * i) * 68 + ty + 16 * j] = accV[i][j];
    __syncthreads();
    for (int idx = tid; idx < 512; idx += 256) {
        int px = idx >> 4, q = idx & 15;
        float4 val = *(const float4*)&so[px * 68 + q * 4];
        *(float4*)&vout[(size_t)(m0 + px) * 64 + q * 4] = val;
    }
}

// ---------------------------------------------------------------------------
// Attention: warp per pixel, grid (4096, 3 dilations). 9-tap softmax.
// float2-vectorized channel loads. OOB taps contribute logit EXACTLY 0.
// ---------------------------------------------------------------------------
__global__ __launch_bounds__(256) void attn_kernel()
{
    int dil_idx = blockIdx.y;
    int dil = dil_idx + 1;
    int warp = threadIdx.x >> 5, lane = threadIdx.x & 31;
    int m = blockIdx.x * 8 + warp;
    int b = m >> 12, hw = m & 4095, h = hw >> 6, w = hw & 63;
    const float* q = &g_qkv[(size_t)dil_idx * Mm * HD];
    const float *kb, *vb;
    if (dil_idx == 0) {
        kb = &g_qkv[(size_t)3 * Mm * HD];
        vb = &g_qkv[(size_t)6 * Mm * HD];
    } else {
        kb = g_defk[dil_idx - 1];
        vb = g_defv[dil_idx - 1];
    }
    float2 q01 = *(const float2*)&q[(size_t)m * 64 + lane * 2];
    float eg[9];
    int nb[9];
    float mx = -1e30f;
    #pragma unroll
    for (int j = 0; j < 9; j++) {
        int y = h + (j / 3 - 1) * dil;
        int x = w + (j % 3 - 1) * dil;
        bool valid = ((unsigned)y < 64u) && ((unsigned)x < 64u);
        float p = 0.f;
        int base = -1;
        if (valid) {
            base = (b << 12) + (y << 6) + x;
            float2 k2 = *(const float2*)&kb[(size_t)base * 64 + lane * 2];
            p = q01.x * k2.x + q01.y * k2.y;
        }
        nb[j] = base;
        #pragma unroll
        for (int s = 16; s; s >>= 1) p += __shfl_xor_sync(0xffffffffu, p, s);
        eg[j] = p * 0.125f;
        mx = fmaxf(mx, eg[j]);
    }
    float sum = 0.f;
    #pragma unroll
    for (int j = 0; j < 9; j++) { eg[j] = expf(eg[j] - mx); sum += eg[j]; }
    float inv = 1.f / sum;
    float o0 = 0.f, o1 = 0.f;
    #pragma unroll
    for (int j = 0; j < 9; j++) {
        if (nb[j] >= 0) {
            float a = eg[j] * inv;
            float2 v2 = *(const float2*)&vb[(size_t)nb[j] * 64 + lane * 2];
            o0 += a * v2.x;
            o1 += a * v2.y;
        }
    }
    float2 o = {o0, o1};
    *(float2*)&g_attn[(size_t)m * 192 + dil_idx * 64 + lane * 2] = o;
}

// ---------------------------------------------------------------------------
extern "C" void kernel_launch(void* const* d_in, const int* in_sizes, int n_in,
                              void* d_out, int out_size)
{
    const float* x      = (const float*)d_in[0];
    const float* qkv_w  = (const float*)d_in[1];
    const float* proj_w = (const float*)d_in[2];
    const float* proj_b = (const float*)d_in[3];
    const float* off_w2 = (const float*)d_in[4];
    const float* off_b2 = (const float*)d_in[5];
    const float* def_w2 = (const float*)d_in[6];
    const float* def_b2 = (const float*)d_in[7];
    const float* off_w3 = (const float*)d_in[8];
    const float* off_b3 = (const float*)d_in[9];
    const float* def_w3 = (const float*)d_in[10];
    const float* def_b3 = (const float*)d_in[11];
    float* out = (float*)d_out;

    // 0) one-time deform-weight transpose (tiny)
    wtrans_kernel<<<288, 256>>>(def_w2, def_w3);

    // 1) qkv projection: (32768 x 192) @ (192 x 576) -> per-branch buffers
    sgemm_kernel<<<dim3(256, 9), 256>>>(x, qkv_w, nullptr, nullptr, 0);

    // 2) offset convs (dil 2, 3 merged)
    offconv_kernel<<<dim3(1024, 2), 256>>>(off_w2, off_b2, off_w3, off_b3);

    // 3) deformable conv on k and v (dil 2, 3 merged)
    deform_kernel<<<dim3(1024, 2), 256>>>(def_b2, def_b3);

    // 4) local attention, all 3 dilations
    attn_kernel<<<dim3(4096, 3), 256>>>();

    // 5) output projection + bias -> d_out
    sgemm_kernel<<<dim3(256, 3), 256>>>(nullptr, proj_w, proj_b, out, 1);
}